// round 1
// baseline (speedup 1.0000x reference)
#include <cuda_runtime.h>

// Problem constants
static const int S_TOK = 4096;   // H*W tokens
static const int C_DIM = 512;    // channels
static const int D_DIM = 512;    // model dim
static const int BATCH = 4;

// Scratch (device globals; no allocations allowed)
__device__ float g_Q[(size_t)BATCH * S_TOK * D_DIM];   // 32 MB
__device__ float g_K[(size_t)BATCH * S_TOK * D_DIM];   // 32 MB
__device__ float g_V[(size_t)BATCH * S_TOK * D_DIM];   // 32 MB
__device__ float g_O[(size_t)BATCH * S_TOK * D_DIM];   // 32 MB
__device__ float g_P[(size_t)BATCH * S_TOK * S_TOK];   // 256 MB

// ---------------------------------------------------------------------------
// Generic 128x128x16 register-tiled fp32 GEMM.
//   C[m,n] = scale * sum_k A(m,k) * B(n,k)  (+ bias[n])
// AMODE/BMODE: 0 -> element (m,k) at A[k*lda + m]   (m contiguous)
//              1 -> element (m,k) at A[m*lda + k]   (k contiguous)
// STORE_T:     0 -> C[m*ldc + n]
//              1 -> C[n*ldc + m]   (transposed store, m contiguous)
// ---------------------------------------------------------------------------
template<int AMODE, int BMODE, int STORE_T, int HAS_BIAS>
__global__ __launch_bounds__(256)
void gemm_f32(const float* __restrict__ A, int lda, long aStride,
              const float* __restrict__ Bm, int ldb, long bStride,
              float* __restrict__ Cm, int ldc, long cStride,
              const float* __restrict__ bias, float scale, int Kdim)
{
    __shared__ float As[16][132];
    __shared__ float Bs[16][132];

    const int m0 = blockIdx.x * 128;
    const int n0 = blockIdx.y * 128;
    A  += (long)blockIdx.z * aStride;
    Bm += (long)blockIdx.z * bStride;
    Cm += (long)blockIdx.z * cStride;

    const int tid = threadIdx.x;
    const int tx = tid & 15;
    const int ty = tid >> 4;

    float acc[8][8];
    #pragma unroll
    for (int i = 0; i < 8; i++)
        #pragma unroll
        for (int j = 0; j < 8; j++) acc[i][j] = 0.f;

    for (int k0 = 0; k0 < Kdim; k0 += 16) {
        // ---- load A tile -> As[kk][m] ----
        if (AMODE == 0) {
            #pragma unroll
            for (int i = 0; i < 2; i++) {
                int f  = tid + i * 256;
                int kk = f >> 5;            // 32 float4 per 128-wide row
                int m4 = (f & 31) << 2;
                float4 v = *(const float4*)(A + (long)(k0 + kk) * lda + m0 + m4);
                *(float4*)&As[kk][m4] = v;
            }
        } else {
            #pragma unroll
            for (int i = 0; i < 2; i++) {
                int f  = tid + i * 256;
                int m  = f >> 2;
                int k4 = (f & 3) << 2;
                float4 v = *(const float4*)(A + (long)(m0 + m) * lda + k0 + k4);
                As[k4 + 0][m] = v.x; As[k4 + 1][m] = v.y;
                As[k4 + 2][m] = v.z; As[k4 + 3][m] = v.w;
            }
        }
        // ---- load B tile -> Bs[kk][n] ----
        if (BMODE == 0) {
            #pragma unroll
            for (int i = 0; i < 2; i++) {
                int f  = tid + i * 256;
                int kk = f >> 5;
                int n4 = (f & 31) << 2;
                float4 v = *(const float4*)(Bm + (long)(k0 + kk) * ldb + n0 + n4);
                *(float4*)&Bs[kk][n4] = v;
            }
        } else {
            #pragma unroll
            for (int i = 0; i < 2; i++) {
                int f  = tid + i * 256;
                int n  = f >> 2;
                int k4 = (f & 3) << 2;
                float4 v = *(const float4*)(Bm + (long)(n0 + n) * ldb + k0 + k4);
                Bs[k4 + 0][n] = v.x; Bs[k4 + 1][n] = v.y;
                Bs[k4 + 2][n] = v.z; Bs[k4 + 3][n] = v.w;
            }
        }
        __syncthreads();

        #pragma unroll
        for (int kk = 0; kk < 16; kk++) {
            float a[8], b[8];
            *(float4*)&a[0] = *(const float4*)&As[kk][ty << 2];
            *(float4*)&a[4] = *(const float4*)&As[kk][64 + (ty << 2)];
            *(float4*)&b[0] = *(const float4*)&Bs[kk][tx << 2];
            *(float4*)&b[4] = *(const float4*)&Bs[kk][64 + (tx << 2)];
            #pragma unroll
            for (int i = 0; i < 8; i++)
                #pragma unroll
                for (int j = 0; j < 8; j++)
                    acc[i][j] += a[i] * b[j];
        }
        __syncthreads();
    }

    // ---- epilogue ----
    int mrow[8], ncol[8];
    #pragma unroll
    for (int i = 0; i < 4; i++) {
        mrow[i]     = (ty << 2) + i;
        mrow[i + 4] = 64 + (ty << 2) + i;
    }
    #pragma unroll
    for (int j = 0; j < 4; j++) {
        ncol[j]     = (tx << 2) + j;
        ncol[j + 4] = 64 + (tx << 2) + j;
    }

    float bval[8];
    #pragma unroll
    for (int j = 0; j < 8; j++)
        bval[j] = HAS_BIAS ? bias[n0 + ncol[j]] : 0.f;

    if (STORE_T == 0) {
        #pragma unroll
        for (int i = 0; i < 8; i++) {
            float4 v0, v1;
            v0.x = acc[i][0] * scale + bval[0];
            v0.y = acc[i][1] * scale + bval[1];
            v0.z = acc[i][2] * scale + bval[2];
            v0.w = acc[i][3] * scale + bval[3];
            v1.x = acc[i][4] * scale + bval[4];
            v1.y = acc[i][5] * scale + bval[5];
            v1.z = acc[i][6] * scale + bval[6];
            v1.w = acc[i][7] * scale + bval[7];
            float* row = Cm + (long)(m0 + mrow[i]) * ldc + n0;
            *(float4*)(row + (tx << 2))      = v0;
            *(float4*)(row + 64 + (tx << 2)) = v1;
        }
    } else {
        #pragma unroll
        for (int j = 0; j < 8; j++) {
            float4 v0, v1;
            v0.x = acc[0][j] * scale + bval[j];
            v0.y = acc[1][j] * scale + bval[j];
            v0.z = acc[2][j] * scale + bval[j];
            v0.w = acc[3][j] * scale + bval[j];
            v1.x = acc[4][j] * scale + bval[j];
            v1.y = acc[5][j] * scale + bval[j];
            v1.z = acc[6][j] * scale + bval[j];
            v1.w = acc[7][j] * scale + bval[j];
            float* col = Cm + (long)(n0 + ncol[j]) * ldc + m0;
            *(float4*)(col + (ty << 2))      = v0;
            *(float4*)(col + 64 + (ty << 2)) = v1;
        }
    }
}

// ---------------------------------------------------------------------------
// Row softmax over 4096-wide rows. One block (256 threads) per row.
// ---------------------------------------------------------------------------
__global__ __launch_bounds__(256)
void softmax_rows(float* __restrict__ P)
{
    float4* p4 = (float4*)(P + (long)blockIdx.x * S_TOK);
    const int tid = threadIdx.x;

    float4 vv[4];
    float mx = -3.4e38f;
    #pragma unroll
    for (int i = 0; i < 4; i++) {
        vv[i] = p4[tid + (i << 8)];
        mx = fmaxf(mx, fmaxf(fmaxf(vv[i].x, vv[i].y), fmaxf(vv[i].z, vv[i].w)));
    }

    __shared__ float red[8];
    #pragma unroll
    for (int o = 16; o > 0; o >>= 1)
        mx = fmaxf(mx, __shfl_xor_sync(0xffffffffu, mx, o));
    if ((tid & 31) == 0) red[tid >> 5] = mx;
    __syncthreads();
    float m = red[0];
    #pragma unroll
    for (int w = 1; w < 8; w++) m = fmaxf(m, red[w]);
    __syncthreads();

    float s = 0.f;
    #pragma unroll
    for (int i = 0; i < 4; i++) {
        vv[i].x = __expf(vv[i].x - m);
        vv[i].y = __expf(vv[i].y - m);
        vv[i].z = __expf(vv[i].z - m);
        vv[i].w = __expf(vv[i].w - m);
        s += vv[i].x + vv[i].y + vv[i].z + vv[i].w;
    }
    #pragma unroll
    for (int o = 16; o > 0; o >>= 1)
        s += __shfl_xor_sync(0xffffffffu, s, o);
    if ((tid & 31) == 0) red[tid >> 5] = s;
    __syncthreads();
    float tot = red[0];
    #pragma unroll
    for (int w = 1; w < 8; w++) tot += red[w];

    float inv = 1.0f / tot;
    #pragma unroll
    for (int i = 0; i < 4; i++) {
        vv[i].x *= inv; vv[i].y *= inv; vv[i].z *= inv; vv[i].w *= inv;
        p4[tid + (i << 8)] = vv[i];
    }
}

// ---------------------------------------------------------------------------
extern "C" void kernel_launch(void* const* d_in, const int* in_sizes, int n_in,
                              void* d_out, int out_size)
{
    const float* x  = (const float*)d_in[0];   // (B, C, S) channel-major
    const float* Wq = (const float*)d_in[1];   // (D, C)
    const float* bq = (const float*)d_in[2];
    const float* Wk = (const float*)d_in[3];
    const float* bk = (const float*)d_in[4];
    const float* Wv = (const float*)d_in[5];
    const float* bv = (const float*)d_in[6];
    const float* Wo = (const float*)d_in[7];   // (C, D)
    const float* bo = (const float*)d_in[8];
    float* out = (float*)d_out;                // (B, C, H, W) == (B, C, S)

    float *Q, *K, *V, *O, *P;
    cudaGetSymbolAddress((void**)&Q, g_Q);
    cudaGetSymbolAddress((void**)&K, g_K);
    cudaGetSymbolAddress((void**)&V, g_V);
    cudaGetSymbolAddress((void**)&O, g_O);
    cudaGetSymbolAddress((void**)&P, g_P);

    const long SD = (long)S_TOK * D_DIM;
    const long SS = (long)S_TOK * S_TOK;
    const long CS = (long)C_DIM * S_TOK;
    const float attn_scale = 0.044194173824159216f;  // 512^-0.5

    dim3 gProj(S_TOK / 128, D_DIM / 128, BATCH);     // (32, 4, 4)
    dim3 gSim (S_TOK / 128, S_TOK / 128, BATCH);     // (32, 32, 4)
    dim3 gOut (S_TOK / 128, C_DIM / 128, BATCH);     // (32, 4, 4)

    // Q/K/V projections: Q[t,d] = sum_c x[c,t] * W[d,c] + b[d]
    gemm_f32<0,1,0,1><<<gProj, 256>>>(x, S_TOK, CS, Wq, C_DIM, 0, Q, D_DIM, SD, bq, 1.f, C_DIM);
    gemm_f32<0,1,0,1><<<gProj, 256>>>(x, S_TOK, CS, Wk, C_DIM, 0, K, D_DIM, SD, bk, 1.f, C_DIM);
    gemm_f32<0,1,0,1><<<gProj, 256>>>(x, S_TOK, CS, Wv, C_DIM, 0, V, D_DIM, SD, bv, 1.f, C_DIM);

    // sim = scale * Q K^T
    gemm_f32<1,1,0,0><<<gSim, 256>>>(Q, D_DIM, SD, K, D_DIM, SD, P, S_TOK, SS,
                                     nullptr, attn_scale, D_DIM);

    // softmax over rows
    softmax_rows<<<BATCH * S_TOK, 256>>>(P);

    // O = attn @ V
    gemm_f32<1,0,0,0><<<gProj, 256>>>(P, S_TOK, SS, V, D_DIM, SD, O, D_DIM, SD,
                                      nullptr, 1.f, S_TOK);

    // y[c,t] = sum_d O[t,d] * Wo[c,d] + bo[c]  (transposed store)
    gemm_f32<1,1,1,1><<<gOut, 256>>>(O, D_DIM, SD, Wo, D_DIM, 0, out, S_TOK, CS,
                                     bo, 1.f, D_DIM);
}

// round 3
// speedup vs baseline: 2.4576x; 2.4576x over previous
#include <cuda_runtime.h>
#include <cuda_bf16.h>
#include <cstdint>

#define S_TOK 4096
#define C_DIM 512
#define D_DIM 512
#define BATCH 4

// ---------------------------------------------------------------------------
// Scratch (device globals; no allocations allowed)
// ---------------------------------------------------------------------------
__device__ __nv_bfloat16 g_xh[(size_t)BATCH * S_TOK * C_DIM];
__device__ __nv_bfloat16 g_xl[(size_t)BATCH * S_TOK * C_DIM];
__device__ __nv_bfloat16 g_Wqh[D_DIM * C_DIM], g_Wql[D_DIM * C_DIM];
__device__ __nv_bfloat16 g_Wkh[D_DIM * C_DIM], g_Wkl[D_DIM * C_DIM];
__device__ __nv_bfloat16 g_Wvh[D_DIM * C_DIM], g_Wvl[D_DIM * C_DIM];
__device__ __nv_bfloat16 g_Woh[C_DIM * D_DIM], g_Wol[C_DIM * D_DIM];
__device__ __nv_bfloat16 g_Qh[(size_t)BATCH * S_TOK * D_DIM];
__device__ __nv_bfloat16 g_Ql[(size_t)BATCH * S_TOK * D_DIM];
__device__ __nv_bfloat16 g_Kh[(size_t)BATCH * S_TOK * D_DIM];
__device__ __nv_bfloat16 g_Kl[(size_t)BATCH * S_TOK * D_DIM];
__device__ __nv_bfloat16 g_Vth[(size_t)BATCH * D_DIM * S_TOK];
__device__ __nv_bfloat16 g_Vtl[(size_t)BATCH * D_DIM * S_TOK];
__device__ float         g_P [(size_t)BATCH * S_TOK * S_TOK];
__device__ __nv_bfloat16 g_Ph[(size_t)BATCH * S_TOK * S_TOK];
__device__ __nv_bfloat16 g_Pl[(size_t)BATCH * S_TOK * S_TOK];
__device__ __nv_bfloat16 g_Oh[(size_t)BATCH * S_TOK * D_DIM];
__device__ __nv_bfloat16 g_Ol[(size_t)BATCH * S_TOK * D_DIM];

// ---------------------------------------------------------------------------
// PTX helpers (sm_103-portable: mma.sync / ldmatrix / cp.async only)
// ---------------------------------------------------------------------------
__device__ __forceinline__ uint32_t smem_u32(const void* p) {
    uint32_t a;
    asm("{ .reg .u64 t; cvta.to.shared.u64 t, %1; cvt.u32.u64 %0, t; }"
        : "=r"(a) : "l"(p));
    return a;
}

#define CP16(dst, src) \
    asm volatile("cp.async.cg.shared.global [%0], [%1], 16;" \
                 :: "r"(dst), "l"(src) : "memory")
#define CP_COMMIT() asm volatile("cp.async.commit_group;" ::: "memory")
#define CP_WAIT(n)  asm volatile("cp.async.wait_group %0;" :: "n"(n) : "memory")

#define LDSM_X4(r, addr)                                                      \
    asm volatile("ldmatrix.sync.aligned.m8n8.x4.shared.b16 {%0,%1,%2,%3}, [%4];" \
                 : "=r"((r)[0]), "=r"((r)[1]), "=r"((r)[2]), "=r"((r)[3])     \
                 : "r"(addr))

#define MMA16816(d, a, b0, b1)                                                \
    asm volatile("mma.sync.aligned.m16n8k16.row.col.f32.bf16.bf16.f32 "      \
                 "{%0,%1,%2,%3}, {%4,%5,%6,%7}, {%8,%9}, {%0,%1,%2,%3};"     \
                 : "+f"((d)[0]), "+f"((d)[1]), "+f"((d)[2]), "+f"((d)[3])    \
                 : "r"((a)[0]), "r"((a)[1]), "r"((a)[2]), "r"((a)[3]),       \
                   "r"(b0), "r"(b1))

// ---------------------------------------------------------------------------
// Split-bf16 mma.sync GEMM: C(M,N) = scale * (sum_k A(m,k)*B(n,k) + bias[n])
// A,B k-contiguous (lda = ldb = Ktot), split into hi/lo bf16 planes.
// CTA: 128x128 tile, 8 warps of 64x32. K chunked by 32, cp.async double-buffer.
// Smem tile: 128 rows x 80B (32 bf16 padded to 40) -> conflict-free ldmatrix.
// ---------------------------------------------------------------------------
#define TILE_B   10240            // 128 * 80
#define STAGE_B  (4 * TILE_B)     // Ah, Al, Bh, Bl
#define GEMM_SMEM (2 * STAGE_B)   // double buffered

template<int SPLIT_OUT, int TRANS, int HAS_BIAS>
__global__ __launch_bounds__(256)
void gemm_mma(const __nv_bfloat16* __restrict__ Ah, const __nv_bfloat16* __restrict__ Al,
              long aStride, int Ktot,
              const __nv_bfloat16* __restrict__ Bh, const __nv_bfloat16* __restrict__ Bl,
              long bStride,
              float* __restrict__ Cf, __nv_bfloat16* __restrict__ Ch,
              __nv_bfloat16* __restrict__ Cl, long cStride, int ldc,
              const float* __restrict__ bias, float scale)
{
    extern __shared__ char sm[];
    const uint32_t sbase = smem_u32(sm);

    const int tid  = threadIdx.x;
    const int lane = tid & 31;
    const int wid  = tid >> 5;
    const int m0 = blockIdx.x * 128;
    const int n0 = blockIdx.y * 128;
    const int bz = blockIdx.z;

    const __nv_bfloat16* ArowH = Ah + (long)bz * aStride + (long)m0 * Ktot;
    const __nv_bfloat16* ArowL = Al + (long)bz * aStride + (long)m0 * Ktot;
    const __nv_bfloat16* BrowH = Bh + (long)bz * bStride + (long)n0 * Ktot;
    const __nv_bfloat16* BrowL = Bl + (long)bz * bStride + (long)n0 * Ktot;

    // global->smem stage of one 32-wide K chunk (4 tiles of 128x32 bf16)
    const int ldrow = tid >> 2;          // 0..63  (x2 via +64)
    const int ldq   = tid & 3;           // 16B quarter within 64B row
    auto stage_load = [&](int c, int buf) {
        const long kof = (long)c << 5;
        const uint32_t s0 = sbase + buf * STAGE_B;
        #pragma unroll
        for (int i = 0; i < 2; i++) {
            const int row = ldrow + i * 64;
            const uint32_t doff = (uint32_t)(row * 80 + ldq * 16);
            const long goff = (long)row * Ktot + kof + ldq * 8;
            CP16(s0 + doff,              ArowH + goff);
            CP16(s0 + TILE_B + doff,     ArowL + goff);
            CP16(s0 + 2 * TILE_B + doff, BrowH + goff);
            CP16(s0 + 3 * TILE_B + doff, BrowL + goff);
        }
    };

    float acc[4][4][4];
    #pragma unroll
    for (int i = 0; i < 4; i++)
        #pragma unroll
        for (int j = 0; j < 4; j++)
            #pragma unroll
            for (int q = 0; q < 4; q++) acc[i][j][q] = 0.f;

    // warp tile: 64 (M) x 32 (N); 2 warps along M, 4 along N
    const int wr = wid & 1;
    const int wc = wid >> 1;

    // ldmatrix addresses
    const uint32_t aAddr0 = (uint32_t)((wr * 64 + (lane & 15)) * 80 + ((lane >> 4) << 4));
    const uint32_t bRow   = (uint32_t)(wc * 32 + ((lane >> 4) << 3) + (lane & 7));
    const uint32_t bAddr0 = (uint32_t)(bRow * 80 + (((lane >> 3) & 1) << 4));

    const int nCh = Ktot >> 5;
    stage_load(0, 0);
    CP_COMMIT();

    for (int c = 0; c < nCh; c++) {
        const int buf = c & 1;
        if (c + 1 < nCh) {
            stage_load(c + 1, buf ^ 1);
            CP_COMMIT();
            CP_WAIT(1);
        } else {
            CP_WAIT(0);
        }
        __syncthreads();

        const uint32_t s0 = sbase + buf * STAGE_B;
        #pragma unroll
        for (int k16 = 0; k16 < 2; k16++) {
            const uint32_t aA = s0 + aAddr0 + k16 * 32;
            const uint32_t bA = s0 + 2 * TILE_B + bAddr0 + k16 * 32;

            uint32_t ah[4][4], al[4][4], bb[2][4];
            #pragma unroll
            for (int mi = 0; mi < 4; mi++) LDSM_X4(ah[mi], aA + mi * 1280);
            #pragma unroll
            for (int mi = 0; mi < 4; mi++) LDSM_X4(al[mi], aA + TILE_B + mi * 1280);
            #pragma unroll
            for (int ng = 0; ng < 2; ng++) LDSM_X4(bb[ng], bA + ng * 1280);

            // Ah * Bh
            #pragma unroll
            for (int mi = 0; mi < 4; mi++)
                #pragma unroll
                for (int n8 = 0; n8 < 4; n8++)
                    MMA16816(acc[mi][n8], ah[mi],
                             bb[n8 >> 1][(n8 & 1) * 2], bb[n8 >> 1][(n8 & 1) * 2 + 1]);
            // Al * Bh
            #pragma unroll
            for (int mi = 0; mi < 4; mi++)
                #pragma unroll
                for (int n8 = 0; n8 < 4; n8++)
                    MMA16816(acc[mi][n8], al[mi],
                             bb[n8 >> 1][(n8 & 1) * 2], bb[n8 >> 1][(n8 & 1) * 2 + 1]);
            // reload B low plane, Ah * Bl
            #pragma unroll
            for (int ng = 0; ng < 2; ng++) LDSM_X4(bb[ng], bA + TILE_B + ng * 1280);
            #pragma unroll
            for (int mi = 0; mi < 4; mi++)
                #pragma unroll
                for (int n8 = 0; n8 < 4; n8++)
                    MMA16816(acc[mi][n8], ah[mi],
                             bb[n8 >> 1][(n8 & 1) * 2], bb[n8 >> 1][(n8 & 1) * 2 + 1]);
        }
        __syncthreads();
    }

    // ---- epilogue ----
    const int tq = lane >> 2;
    const int tr = lane & 3;
    const int rbase = m0 + wr * 64 + tq;
    const int cbase = n0 + wc * 32 + tr * 2;

    #pragma unroll
    for (int mi = 0; mi < 4; mi++) {
        #pragma unroll
        for (int n8 = 0; n8 < 4; n8++) {
            const int r  = rbase + mi * 16;
            const int cc = cbase + n8 * 8;
            const float b0 = HAS_BIAS ? bias[cc]     : 0.f;
            const float b1 = HAS_BIAS ? bias[cc + 1] : 0.f;
            const float v00 = (acc[mi][n8][0] + b0) * scale;
            const float v01 = (acc[mi][n8][1] + b1) * scale;
            const float v10 = (acc[mi][n8][2] + b0) * scale;
            const float v11 = (acc[mi][n8][3] + b1) * scale;

            if (SPLIT_OUT == 0) {
                if (TRANS == 0) {
                    float* base = Cf + (long)bz * cStride;
                    *reinterpret_cast<float2*>(base + (long)r * ldc + cc)       = make_float2(v00, v01);
                    *reinterpret_cast<float2*>(base + (long)(r + 8) * ldc + cc) = make_float2(v10, v11);
                } else {
                    float* base = Cf + (long)bz * cStride;
                    base[(long)cc * ldc + r]           = v00;
                    base[(long)(cc + 1) * ldc + r]     = v01;
                    base[(long)cc * ldc + r + 8]       = v10;
                    base[(long)(cc + 1) * ldc + r + 8] = v11;
                }
            } else {
                if (TRANS == 0) {
                    __nv_bfloat16* bH = Ch + (long)bz * cStride;
                    __nv_bfloat16* bL = Cl + (long)bz * cStride;
                    __nv_bfloat16 h00 = __float2bfloat16(v00), h01 = __float2bfloat16(v01);
                    __nv_bfloat16 h10 = __float2bfloat16(v10), h11 = __float2bfloat16(v11);
                    __nv_bfloat162 hp0 = __halves2bfloat162(h00, h01);
                    __nv_bfloat162 hp1 = __halves2bfloat162(h10, h11);
                    __nv_bfloat162 lp0 = __halves2bfloat162(
                        __float2bfloat16(v00 - __bfloat162float(h00)),
                        __float2bfloat16(v01 - __bfloat162float(h01)));
                    __nv_bfloat162 lp1 = __halves2bfloat162(
                        __float2bfloat16(v10 - __bfloat162float(h10)),
                        __float2bfloat16(v11 - __bfloat162float(h11)));
                    *reinterpret_cast<__nv_bfloat162*>(bH + (long)r * ldc + cc)       = hp0;
                    *reinterpret_cast<__nv_bfloat162*>(bH + (long)(r + 8) * ldc + cc) = hp1;
                    *reinterpret_cast<__nv_bfloat162*>(bL + (long)r * ldc + cc)       = lp0;
                    *reinterpret_cast<__nv_bfloat162*>(bL + (long)(r + 8) * ldc + cc) = lp1;
                } else {
                    __nv_bfloat16* bH = Ch + (long)bz * cStride;
                    __nv_bfloat16* bL = Cl + (long)bz * cStride;
                    const float vv[4] = {v00, v01, v10, v11};
                    const int rr[4] = {r, r, r + 8, r + 8};
                    const int nn[4] = {cc, cc + 1, cc, cc + 1};
                    #pragma unroll
                    for (int q = 0; q < 4; q++) {
                        __nv_bfloat16 h = __float2bfloat16(vv[q]);
                        bH[(long)nn[q] * ldc + rr[q]] = h;
                        bL[(long)nn[q] * ldc + rr[q]] =
                            __float2bfloat16(vv[q] - __bfloat162float(h));
                    }
                }
            }
        }
    }
}

// ---------------------------------------------------------------------------
// Prep: transpose+split x (B,C,S) -> xh/xl (B,S,C)
// ---------------------------------------------------------------------------
__global__ __launch_bounds__(256)
void split_transpose_x(const float* __restrict__ x,
                       __nv_bfloat16* __restrict__ xh, __nv_bfloat16* __restrict__ xl)
{
    __shared__ float t[32][33];
    const int b = blockIdx.z;
    const int s0 = blockIdx.x << 5, c0 = blockIdx.y << 5;
    const float* xb = x + (long)b * C_DIM * S_TOK;
    const int a = threadIdx.x & 31, q8 = threadIdx.x >> 5;
    #pragma unroll
    for (int i = 0; i < 4; i++) {
        int cc = q8 + (i << 3);
        t[cc][a] = xb[(long)(c0 + cc) * S_TOK + s0 + a];
    }
    __syncthreads();
    const long ob = (long)b * S_TOK * C_DIM;
    #pragma unroll
    for (int i = 0; i < 4; i++) {
        int ss = q8 + (i << 3);
        float v = t[a][ss];
        __nv_bfloat16 h = __float2bfloat16(v);
        __nv_bfloat16 l = __float2bfloat16(v - __bfloat162float(h));
        long idx = ob + (long)(s0 + ss) * C_DIM + c0 + a;
        xh[idx] = h; xl[idx] = l;
    }
}

// Elementwise split for weights
__global__ __launch_bounds__(256)
void split_mat(const float* __restrict__ w,
               __nv_bfloat16* __restrict__ wh, __nv_bfloat16* __restrict__ wl, int n)
{
    int i = blockIdx.x * 256 + threadIdx.x;
    if (i < n) {
        float v = w[i];
        __nv_bfloat16 h = __float2bfloat16(v);
        wh[i] = h;
        wl[i] = __float2bfloat16(v - __bfloat162float(h));
    }
}

// ---------------------------------------------------------------------------
// Row softmax over 4096-wide fp32 rows -> split-bf16 output
// ---------------------------------------------------------------------------
__global__ __launch_bounds__(256)
void softmax_split(const float* __restrict__ P,
                   __nv_bfloat16* __restrict__ Ph, __nv_bfloat16* __restrict__ Pl)
{
    const long row = blockIdx.x;
    const float4* p4 = reinterpret_cast<const float4*>(P + row * S_TOK);
    const int tid = threadIdx.x;

    float4 vv[4];
    float mx = -3.4e38f;
    #pragma unroll
    for (int i = 0; i < 4; i++) {
        vv[i] = p4[tid + (i << 8)];
        mx = fmaxf(mx, fmaxf(fmaxf(vv[i].x, vv[i].y), fmaxf(vv[i].z, vv[i].w)));
    }

    __shared__ float red[8];
    #pragma unroll
    for (int o = 16; o > 0; o >>= 1)
        mx = fmaxf(mx, __shfl_xor_sync(0xffffffffu, mx, o));
    if ((tid & 31) == 0) red[tid >> 5] = mx;
    __syncthreads();
    float m = red[0];
    #pragma unroll
    for (int w = 1; w < 8; w++) m = fmaxf(m, red[w]);
    __syncthreads();

    float s = 0.f;
    #pragma unroll
    for (int i = 0; i < 4; i++) {
        vv[i].x = __expf(vv[i].x - m);
        vv[i].y = __expf(vv[i].y - m);
        vv[i].z = __expf(vv[i].z - m);
        vv[i].w = __expf(vv[i].w - m);
        s += vv[i].x + vv[i].y + vv[i].z + vv[i].w;
    }
    #pragma unroll
    for (int o = 16; o > 0; o >>= 1)
        s += __shfl_xor_sync(0xffffffffu, s, o);
    if ((tid & 31) == 0) red[tid >> 5] = s;
    __syncthreads();
    float tot = red[0];
    #pragma unroll
    for (int w = 1; w < 8; w++) tot += red[w];
    const float inv = 1.0f / tot;

    uint2* h2 = reinterpret_cast<uint2*>(Ph + row * S_TOK);
    uint2* l2 = reinterpret_cast<uint2*>(Pl + row * S_TOK);
    #pragma unroll
    for (int i = 0; i < 4; i++) {
        float e0 = vv[i].x * inv, e1 = vv[i].y * inv, e2 = vv[i].z * inv, e3 = vv[i].w * inv;
        __nv_bfloat16 h0 = __float2bfloat16(e0), h1 = __float2bfloat16(e1);
        __nv_bfloat16 h2v = __float2bfloat16(e2), h3 = __float2bfloat16(e3);
        __nv_bfloat16 l0 = __float2bfloat16(e0 - __bfloat162float(h0));
        __nv_bfloat16 l1 = __float2bfloat16(e1 - __bfloat162float(h1));
        __nv_bfloat16 l2v = __float2bfloat16(e2 - __bfloat162float(h2v));
        __nv_bfloat16 l3 = __float2bfloat16(e3 - __bfloat162float(h3));
        __nv_bfloat162 ha = __halves2bfloat162(h0, h1), hb = __halves2bfloat162(h2v, h3);
        __nv_bfloat162 la = __halves2bfloat162(l0, l1), lb = __halves2bfloat162(l2v, l3);
        uint2 hv, lv;
        hv.x = *reinterpret_cast<uint32_t*>(&ha); hv.y = *reinterpret_cast<uint32_t*>(&hb);
        lv.x = *reinterpret_cast<uint32_t*>(&la); lv.y = *reinterpret_cast<uint32_t*>(&lb);
        h2[tid + (i << 8)] = hv;
        l2[tid + (i << 8)] = lv;
    }
}

// ---------------------------------------------------------------------------
extern "C" void kernel_launch(void* const* d_in, const int* in_sizes, int n_in,
                              void* d_out, int out_size)
{
    const float* x  = (const float*)d_in[0];
    const float* Wq = (const float*)d_in[1];
    const float* bq = (const float*)d_in[2];
    const float* Wk = (const float*)d_in[3];
    const float* bk = (const float*)d_in[4];
    const float* Wv = (const float*)d_in[5];
    const float* bv = (const float*)d_in[6];
    const float* Wo = (const float*)d_in[7];
    const float* bo = (const float*)d_in[8];
    float* out = (float*)d_out;

    __nv_bfloat16 *xh, *xl, *Wqh, *Wql, *Wkh, *Wkl, *Wvh, *Wvl, *Woh, *Wol;
    __nv_bfloat16 *Qh, *Ql, *Kh, *Kl, *Vth, *Vtl, *Ph, *Pl, *Oh, *Ol;
    float* P;
    cudaGetSymbolAddress((void**)&xh, g_xh);   cudaGetSymbolAddress((void**)&xl, g_xl);
    cudaGetSymbolAddress((void**)&Wqh, g_Wqh); cudaGetSymbolAddress((void**)&Wql, g_Wql);
    cudaGetSymbolAddress((void**)&Wkh, g_Wkh); cudaGetSymbolAddress((void**)&Wkl, g_Wkl);
    cudaGetSymbolAddress((void**)&Wvh, g_Wvh); cudaGetSymbolAddress((void**)&Wvl, g_Wvl);
    cudaGetSymbolAddress((void**)&Woh, g_Woh); cudaGetSymbolAddress((void**)&Wol, g_Wol);
    cudaGetSymbolAddress((void**)&Qh, g_Qh);   cudaGetSymbolAddress((void**)&Ql, g_Ql);
    cudaGetSymbolAddress((void**)&Kh, g_Kh);   cudaGetSymbolAddress((void**)&Kl, g_Kl);
    cudaGetSymbolAddress((void**)&Vth, g_Vth); cudaGetSymbolAddress((void**)&Vtl, g_Vtl);
    cudaGetSymbolAddress((void**)&P, g_P);
    cudaGetSymbolAddress((void**)&Ph, g_Ph);   cudaGetSymbolAddress((void**)&Pl, g_Pl);
    cudaGetSymbolAddress((void**)&Oh, g_Oh);   cudaGetSymbolAddress((void**)&Ol, g_Ol);

    cudaFuncSetAttribute(gemm_mma<1,0,1>, cudaFuncAttributeMaxDynamicSharedMemorySize, GEMM_SMEM);
    cudaFuncSetAttribute(gemm_mma<1,1,1>, cudaFuncAttributeMaxDynamicSharedMemorySize, GEMM_SMEM);
    cudaFuncSetAttribute(gemm_mma<0,0,0>, cudaFuncAttributeMaxDynamicSharedMemorySize, GEMM_SMEM);
    cudaFuncSetAttribute(gemm_mma<1,0,0>, cudaFuncAttributeMaxDynamicSharedMemorySize, GEMM_SMEM);
    cudaFuncSetAttribute(gemm_mma<0,1,1>, cudaFuncAttributeMaxDynamicSharedMemorySize, GEMM_SMEM);

    const long SD = (long)S_TOK * D_DIM;
    const long SS = (long)S_TOK * S_TOK;
    const long SC = (long)S_TOK * C_DIM;
    const long CS = (long)C_DIM * S_TOK;
    const float attn_scale = 0.044194173824159216f;   // 512^-0.5

    // ---- prep ----
    split_transpose_x<<<dim3(S_TOK / 32, C_DIM / 32, BATCH), 256>>>(x, xh, xl);
    split_mat<<<1024, 256>>>(Wq, Wqh, Wql, D_DIM * C_DIM);
    split_mat<<<1024, 256>>>(Wk, Wkh, Wkl, D_DIM * C_DIM);
    split_mat<<<1024, 256>>>(Wv, Wvh, Wvl, D_DIM * C_DIM);
    split_mat<<<1024, 256>>>(Wo, Woh, Wol, C_DIM * D_DIM);

    dim3 gProj(S_TOK / 128, D_DIM / 128, BATCH);   // (32, 4, 4)
    dim3 gSim (S_TOK / 128, S_TOK / 128, BATCH);   // (32, 32, 4)
    dim3 gOut (S_TOK / 128, C_DIM / 128, BATCH);   // (32, 4, 4)

    // ---- QKV projections (attn scale folded into Q) ----
    gemm_mma<1,0,1><<<gProj, 256, GEMM_SMEM>>>(xh, xl, SC, C_DIM, Wqh, Wql, 0,
        nullptr, Qh, Ql, SD, D_DIM, bq, attn_scale);
    gemm_mma<1,0,1><<<gProj, 256, GEMM_SMEM>>>(xh, xl, SC, C_DIM, Wkh, Wkl, 0,
        nullptr, Kh, Kl, SD, D_DIM, bk, 1.f);
    gemm_mma<1,1,1><<<gProj, 256, GEMM_SMEM>>>(xh, xl, SC, C_DIM, Wvh, Wvl, 0,
        nullptr, Vth, Vtl, SD, S_TOK, bv, 1.f);

    // ---- sim = Q' K^T (fp32 out) ----
    gemm_mma<0,0,0><<<gSim, 256, GEMM_SMEM>>>(Qh, Ql, SD, D_DIM, Kh, Kl, SD,
        P, nullptr, nullptr, SS, S_TOK, nullptr, 1.f);

    // ---- softmax -> split bf16 ----
    softmax_split<<<BATCH * S_TOK, 256>>>(P, Ph, Pl);

    // ---- O = attn @ V  (split out) ----
    gemm_mma<1,0,0><<<gProj, 256, GEMM_SMEM>>>(Ph, Pl, SS, S_TOK, Vth, Vtl, SD,
        nullptr, Oh, Ol, SD, D_DIM, nullptr, 1.f);

    // ---- y = O Wo^T + bo  (fp32, transposed store to (B,C,S)) ----
    gemm_mma<0,1,1><<<gOut, 256, GEMM_SMEM>>>(Oh, Ol, SD, D_DIM, Woh, Wol, 0,
        out, nullptr, nullptr, CS, S_TOK, bo, 1.f);
}

// round 4
// speedup vs baseline: 3.0341x; 1.2346x over previous
#include <cuda_runtime.h>
#include <cuda_fp16.h>
#include <cstdint>

#define S_TOK 4096
#define C_DIM 512
#define D_DIM 512
#define BATCH 4

// ---------------------------------------------------------------------------
// Scratch (device globals; no allocations allowed)
// ---------------------------------------------------------------------------
__device__ __half g_xh[(size_t)BATCH * S_TOK * C_DIM];
__device__ __half g_xl[(size_t)BATCH * S_TOK * C_DIM];
__device__ __half g_Wqh[D_DIM * C_DIM], g_Wql[D_DIM * C_DIM];
__device__ __half g_Wkh[D_DIM * C_DIM], g_Wkl[D_DIM * C_DIM];
__device__ __half g_Wvh[D_DIM * C_DIM], g_Wvl[D_DIM * C_DIM];
__device__ __half g_Woh[C_DIM * D_DIM], g_Wol[C_DIM * D_DIM];
__device__ __half g_Q [(size_t)BATCH * S_TOK * D_DIM];          // scaled, single plane
__device__ __half g_Kh[(size_t)BATCH * S_TOK * D_DIM];
__device__ __half g_Kl[(size_t)BATCH * S_TOK * D_DIM];
__device__ __half g_Vth[(size_t)BATCH * D_DIM * S_TOK];         // V^T (d-major)
__device__ __half g_Vtl[(size_t)BATCH * D_DIM * S_TOK];
__device__ __half g_P [(size_t)BATCH * S_TOK * S_TOK];          // 128 MB, single plane
__device__ __half g_Oh[(size_t)BATCH * S_TOK * D_DIM];
__device__ __half g_Ol[(size_t)BATCH * S_TOK * D_DIM];

// ---------------------------------------------------------------------------
// PTX helpers (sm_103-portable: mma.sync / ldmatrix / cp.async only)
// ---------------------------------------------------------------------------
__device__ __forceinline__ uint32_t smem_u32(const void* p) {
    uint32_t a;
    asm("{ .reg .u64 t; cvta.to.shared.u64 t, %1; cvt.u32.u64 %0, t; }"
        : "=r"(a) : "l"(p));
    return a;
}

#define CP16(dst, src) \
    asm volatile("cp.async.cg.shared.global [%0], [%1], 16;" \
                 :: "r"(dst), "l"(src) : "memory")
#define CP_COMMIT() asm volatile("cp.async.commit_group;" ::: "memory")
#define CP_WAIT(n)  asm volatile("cp.async.wait_group %0;" :: "n"(n) : "memory")

#define LDSM_X4(r, addr)                                                      \
    asm volatile("ldmatrix.sync.aligned.m8n8.x4.shared.b16 {%0,%1,%2,%3}, [%4];" \
                 : "=r"((r)[0]), "=r"((r)[1]), "=r"((r)[2]), "=r"((r)[3])     \
                 : "r"(addr))

#define MMA16816(d, a, b0, b1)                                                \
    asm volatile("mma.sync.aligned.m16n8k16.row.col.f32.f16.f16.f32 "        \
                 "{%0,%1,%2,%3}, {%4,%5,%6,%7}, {%8,%9}, {%0,%1,%2,%3};"     \
                 : "+f"((d)[0]), "+f"((d)[1]), "+f"((d)[2]), "+f"((d)[3])    \
                 : "r"((a)[0]), "r"((a)[1]), "r"((a)[2]), "r"((a)[3]),       \
                   "r"(b0), "r"(b1))

// One full 64x64x16 warp pass: 4 mi x 8 n8 MMAs
#define MMA_PASS(af, bf)                                                      \
    _Pragma("unroll")                                                         \
    for (int mi = 0; mi < 4; mi++) {                                          \
        _Pragma("unroll")                                                     \
        for (int ng = 0; ng < 4; ng++) {                                      \
            MMA16816(acc[mi][2 * ng],     (af)[mi], (bf)[ng][0], (bf)[ng][1]); \
            MMA16816(acc[mi][2 * ng + 1], (af)[mi], (bf)[ng][2], (bf)[ng][3]); \
        }                                                                     \
    }

// ---------------------------------------------------------------------------
// Split-fp16 mma.sync GEMM: C(M,N) = scale * (sum_k A(m,k)*B(n,k) + bias[n])
// A,B k-contiguous (lda = ldb = Ktot). B always hi+lo planes.
// APASS: 1 -> passes Ah*Bh + Ah*Bl         (error ~2^-12, big GEMMs)
//        2 -> passes Ah*Bh + Al*Bh + Ah*Bl (error ~2^-24, small GEMMs)
// OUTMODE: 0 = fp32, 1 = split fp16 (hi+lo), 2 = single fp16
// CTA tile 256(M) x 128(N), 8 warps of 64x64; K chunked by 32, double-buffered.
// Smem rows padded to 80B -> conflict-free ldmatrix.
// ---------------------------------------------------------------------------
template<int APASS, int OUTMODE, int TRANS, int HAS_BIAS>
__global__ __launch_bounds__(256)
void gemm2(const __half* __restrict__ Ah, const __half* __restrict__ Al,
           long aStride, int Ktot,
           const __half* __restrict__ Bh, const __half* __restrict__ Bl,
           long bStride,
           float* __restrict__ Cf, __half* __restrict__ Ch,
           __half* __restrict__ Cl, long cStride, int ldc,
           const float* __restrict__ bias, float scale)
{
    constexpr int AH_OFF = 0;
    constexpr int AL_OFF = 20480;
    constexpr int BH_OFF = (APASS == 2) ? 40960 : 20480;
    constexpr int BL_OFF = BH_OFF + 10240;
    constexpr int STAGE  = BL_OFF + 10240;

    extern __shared__ char smch[];
    const uint32_t sbase = smem_u32(smch);

    const int tid  = threadIdx.x;
    const int lane = tid & 31;
    const int wid  = tid >> 5;
    const int m0 = blockIdx.x * 256;
    const int n0 = blockIdx.y * 128;
    const int bz = blockIdx.z;

    const __half* ArowH = Ah + (long)bz * aStride + (long)m0 * Ktot;
    const __half* ArowL = (APASS == 2) ? (Al + (long)bz * aStride + (long)m0 * Ktot) : ArowH;
    const __half* BrowH = Bh + (long)bz * bStride + (long)n0 * Ktot;
    const __half* BrowL = Bl + (long)bz * bStride + (long)n0 * Ktot;

    const int ldrow = tid >> 2;     // 0..63
    const int ldq   = tid & 3;      // 16B quarter of 64B row
    auto stage_load = [&](int c, int buf) {
        const long kof = (long)c << 5;
        const uint32_t s0 = sbase + buf * STAGE;
        #pragma unroll
        for (int i = 0; i < 4; i++) {                 // A: 256 rows
            const int row = ldrow + i * 64;
            const uint32_t doff = (uint32_t)(row * 80 + ldq * 16);
            const long goff = (long)row * Ktot + kof + ldq * 8;
            CP16(s0 + AH_OFF + doff, ArowH + goff);
            if (APASS == 2) CP16(s0 + AL_OFF + doff, ArowL + goff);
        }
        #pragma unroll
        for (int i = 0; i < 2; i++) {                 // B: 128 rows, hi+lo
            const int row = ldrow + i * 64;
            const uint32_t doff = (uint32_t)(row * 80 + ldq * 16);
            const long goff = (long)row * Ktot + kof + ldq * 8;
            CP16(s0 + BH_OFF + doff, BrowH + goff);
            CP16(s0 + BL_OFF + doff, BrowL + goff);
        }
    };

    float acc[4][8][4];
    #pragma unroll
    for (int i = 0; i < 4; i++)
        #pragma unroll
        for (int j = 0; j < 8; j++)
            #pragma unroll
            for (int q = 0; q < 4; q++) acc[i][j][q] = 0.f;

    // warp tile 64x64: 4 warps along M, 2 along N
    const int wr = wid & 3;
    const int wc = wid >> 2;

    const uint32_t aAddr0 = (uint32_t)((wr * 64 + (lane & 15)) * 80 + ((lane >> 4) << 4));
    const uint32_t bAddr0 = (uint32_t)((wc * 64 + ((lane >> 4) << 3) + (lane & 7)) * 80
                                       + (((lane >> 3) & 1) << 4));

    const int nCh = Ktot >> 5;
    stage_load(0, 0);
    CP_COMMIT();

    for (int c = 0; c < nCh; c++) {
        const int buf = c & 1;
        if (c + 1 < nCh) {
            stage_load(c + 1, buf ^ 1);
            CP_COMMIT();
            CP_WAIT(1);
        } else {
            CP_WAIT(0);
        }
        __syncthreads();

        const uint32_t s0 = sbase + buf * STAGE;
        #pragma unroll
        for (int k16 = 0; k16 < 2; k16++) {
            const uint32_t aA = s0 + AH_OFF + aAddr0 + k16 * 32;
            const uint32_t bA = s0 + BH_OFF + bAddr0 + k16 * 32;

            uint32_t ah[4][4], bb[4][4];
            #pragma unroll
            for (int mi = 0; mi < 4; mi++) LDSM_X4(ah[mi], aA + mi * 1280);
            #pragma unroll
            for (int ng = 0; ng < 4; ng++) LDSM_X4(bb[ng], bA + ng * 1280);

            MMA_PASS(ah, bb);                         // Ah * Bh

            if (APASS == 2) {
                uint32_t al[4][4];
                #pragma unroll
                for (int mi = 0; mi < 4; mi++)
                    LDSM_X4(al[mi], aA + (AL_OFF - AH_OFF) + mi * 1280);
                MMA_PASS(al, bb);                     // Al * Bh
            }

            #pragma unroll
            for (int ng = 0; ng < 4; ng++)
                LDSM_X4(bb[ng], bA + (BL_OFF - BH_OFF) + ng * 1280);
            MMA_PASS(ah, bb);                         // Ah * Bl
        }
        __syncthreads();
    }

    // ---- epilogue ----
    const int tq = lane >> 2;
    const int tr = lane & 3;

    #pragma unroll
    for (int mi = 0; mi < 4; mi++) {
        #pragma unroll
        for (int n8 = 0; n8 < 8; n8++) {
            const int r  = m0 + wr * 64 + mi * 16 + tq;
            const int cc = n0 + wc * 64 + n8 * 8 + tr * 2;
            const float b0 = HAS_BIAS ? bias[cc]     : 0.f;
            const float b1 = HAS_BIAS ? bias[cc + 1] : 0.f;
            const float v00 = (acc[mi][n8][0] + b0) * scale;
            const float v01 = (acc[mi][n8][1] + b1) * scale;
            const float v10 = (acc[mi][n8][2] + b0) * scale;
            const float v11 = (acc[mi][n8][3] + b1) * scale;

            if (OUTMODE == 0) {
                float* base = Cf + (long)bz * cStride;
                if (TRANS == 0) {
                    *reinterpret_cast<float2*>(base + (long)r * ldc + cc)       = make_float2(v00, v01);
                    *reinterpret_cast<float2*>(base + (long)(r + 8) * ldc + cc) = make_float2(v10, v11);
                } else {
                    base[(long)cc * ldc + r]           = v00;
                    base[(long)(cc + 1) * ldc + r]     = v01;
                    base[(long)cc * ldc + r + 8]       = v10;
                    base[(long)(cc + 1) * ldc + r + 8] = v11;
                }
            } else if (OUTMODE == 2) {
                __half* base = Ch + (long)bz * cStride;
                __half2 p0 = __floats2half2_rn(v00, v01);
                __half2 p1 = __floats2half2_rn(v10, v11);
                *reinterpret_cast<__half2*>(base + (long)r * ldc + cc)       = p0;
                *reinterpret_cast<__half2*>(base + (long)(r + 8) * ldc + cc) = p1;
            } else {  // OUTMODE == 1: split fp16
                __half* bH = Ch + (long)bz * cStride;
                __half* bL = Cl + (long)bz * cStride;
                __half h00 = __float2half_rn(v00), h01 = __float2half_rn(v01);
                __half h10 = __float2half_rn(v10), h11 = __float2half_rn(v11);
                __half l00 = __float2half_rn(v00 - __half2float(h00));
                __half l01 = __float2half_rn(v01 - __half2float(h01));
                __half l10 = __float2half_rn(v10 - __half2float(h10));
                __half l11 = __float2half_rn(v11 - __half2float(h11));
                if (TRANS == 0) {
                    *reinterpret_cast<__half2*>(bH + (long)r * ldc + cc)       = __halves2half2(h00, h01);
                    *reinterpret_cast<__half2*>(bH + (long)(r + 8) * ldc + cc) = __halves2half2(h10, h11);
                    *reinterpret_cast<__half2*>(bL + (long)r * ldc + cc)       = __halves2half2(l00, l01);
                    *reinterpret_cast<__half2*>(bL + (long)(r + 8) * ldc + cc) = __halves2half2(l10, l11);
                } else {
                    bH[(long)cc * ldc + r]           = h00;
                    bH[(long)(cc + 1) * ldc + r]     = h01;
                    bH[(long)cc * ldc + r + 8]       = h10;
                    bH[(long)(cc + 1) * ldc + r + 8] = h11;
                    bL[(long)cc * ldc + r]           = l00;
                    bL[(long)(cc + 1) * ldc + r]     = l01;
                    bL[(long)cc * ldc + r + 8]       = l10;
                    bL[(long)(cc + 1) * ldc + r + 8] = l11;
                }
            }
        }
    }
}

// ---------------------------------------------------------------------------
// Prep: transpose+split x (B,C,S) fp32 -> xh/xl (B,S,C) fp16 planes
// ---------------------------------------------------------------------------
__global__ __launch_bounds__(256)
void split_transpose_x(const float* __restrict__ x,
                       __half* __restrict__ xh, __half* __restrict__ xl)
{
    __shared__ float t[32][33];
    const int b = blockIdx.z;
    const int s0 = blockIdx.x << 5, c0 = blockIdx.y << 5;
    const float* xb = x + (long)b * C_DIM * S_TOK;
    const int a = threadIdx.x & 31, q8 = threadIdx.x >> 5;
    #pragma unroll
    for (int i = 0; i < 4; i++) {
        int cc = q8 + (i << 3);
        t[cc][a] = xb[(long)(c0 + cc) * S_TOK + s0 + a];
    }
    __syncthreads();
    const long ob = (long)b * S_TOK * C_DIM;
    #pragma unroll
    for (int i = 0; i < 4; i++) {
        int ss = q8 + (i << 3);
        float v = t[a][ss];
        __half h = __float2half_rn(v);
        __half l = __float2half_rn(v - __half2float(h));
        long idx = ob + (long)(s0 + ss) * C_DIM + c0 + a;
        xh[idx] = h; xl[idx] = l;
    }
}

__global__ __launch_bounds__(256)
void split_mat(const float* __restrict__ w,
               __half* __restrict__ wh, __half* __restrict__ wl, int n)
{
    int i = blockIdx.x * 256 + threadIdx.x;
    if (i < n) {
        float v = w[i];
        __half h = __float2half_rn(v);
        wh[i] = h;
        wl[i] = __float2half_rn(v - __half2float(h));
    }
}

// ---------------------------------------------------------------------------
// In-place row softmax over 4096-wide fp16 rows (compute in fp32)
// ---------------------------------------------------------------------------
__global__ __launch_bounds__(256)
void softmax_h(__half* __restrict__ P)
{
    const long row = blockIdx.x;
    uint4* p4 = reinterpret_cast<uint4*>(P + row * S_TOK);   // 8 halves per uint4
    const int tid = threadIdx.x;

    uint4 raw[2];
    float v[16];
    #pragma unroll
    for (int i = 0; i < 2; i++) {
        raw[i] = p4[tid + (i << 8)];
        const __half2* h = reinterpret_cast<const __half2*>(&raw[i]);
        #pragma unroll
        for (int j = 0; j < 4; j++) {
            float2 f = __half22float2(h[j]);
            v[i * 8 + j * 2]     = f.x;
            v[i * 8 + j * 2 + 1] = f.y;
        }
    }

    float mx = -3.4e38f;
    #pragma unroll
    for (int j = 0; j < 16; j++) mx = fmaxf(mx, v[j]);

    __shared__ float red[8];
    #pragma unroll
    for (int o = 16; o > 0; o >>= 1)
        mx = fmaxf(mx, __shfl_xor_sync(0xffffffffu, mx, o));
    if ((tid & 31) == 0) red[tid >> 5] = mx;
    __syncthreads();
    float m = red[0];
    #pragma unroll
    for (int w = 1; w < 8; w++) m = fmaxf(m, red[w]);
    __syncthreads();

    float s = 0.f;
    #pragma unroll
    for (int j = 0; j < 16; j++) { v[j] = __expf(v[j] - m); s += v[j]; }
    #pragma unroll
    for (int o = 16; o > 0; o >>= 1)
        s += __shfl_xor_sync(0xffffffffu, s, o);
    if ((tid & 31) == 0) red[tid >> 5] = s;
    __syncthreads();
    float tot = red[0];
    #pragma unroll
    for (int w = 1; w < 8; w++) tot += red[w];
    const float inv = 1.0f / tot;

    #pragma unroll
    for (int i = 0; i < 2; i++) {
        uint4 outp;
        __half2* h = reinterpret_cast<__half2*>(&outp);
        #pragma unroll
        for (int j = 0; j < 4; j++)
            h[j] = __floats2half2_rn(v[i * 8 + j * 2] * inv, v[i * 8 + j * 2 + 1] * inv);
        p4[tid + (i << 8)] = outp;
    }
}

// ---------------------------------------------------------------------------
extern "C" void kernel_launch(void* const* d_in, const int* in_sizes, int n_in,
                              void* d_out, int out_size)
{
    const float* x  = (const float*)d_in[0];
    const float* Wq = (const float*)d_in[1];
    const float* bq = (const float*)d_in[2];
    const float* Wk = (const float*)d_in[3];
    const float* bk = (const float*)d_in[4];
    const float* Wv = (const float*)d_in[5];
    const float* bv = (const float*)d_in[6];
    const float* Wo = (const float*)d_in[7];
    const float* bo = (const float*)d_in[8];
    float* out = (float*)d_out;

    __half *xh, *xl, *Wqh, *Wql, *Wkh, *Wkl, *Wvh, *Wvl, *Woh, *Wol;
    __half *Q, *Kh, *Kl, *Vth, *Vtl, *P, *Oh, *Ol;
    cudaGetSymbolAddress((void**)&xh, g_xh);   cudaGetSymbolAddress((void**)&xl, g_xl);
    cudaGetSymbolAddress((void**)&Wqh, g_Wqh); cudaGetSymbolAddress((void**)&Wql, g_Wql);
    cudaGetSymbolAddress((void**)&Wkh, g_Wkh); cudaGetSymbolAddress((void**)&Wkl, g_Wkl);
    cudaGetSymbolAddress((void**)&Wvh, g_Wvh); cudaGetSymbolAddress((void**)&Wvl, g_Wvl);
    cudaGetSymbolAddress((void**)&Woh, g_Woh); cudaGetSymbolAddress((void**)&Wol, g_Wol);
    cudaGetSymbolAddress((void**)&Q, g_Q);
    cudaGetSymbolAddress((void**)&Kh, g_Kh);   cudaGetSymbolAddress((void**)&Kl, g_Kl);
    cudaGetSymbolAddress((void**)&Vth, g_Vth); cudaGetSymbolAddress((void**)&Vtl, g_Vtl);
    cudaGetSymbolAddress((void**)&P, g_P);
    cudaGetSymbolAddress((void**)&Oh, g_Oh);   cudaGetSymbolAddress((void**)&Ol, g_Ol);

    const int SMEM3 = 2 * 81920;    // APASS==2: 2 * (20480*2 + 10240*2)
    const int SMEM2 = 2 * 40960;    // APASS==1: 2 * (20480 + 10240*2)
    cudaFuncSetAttribute(gemm2<2,2,0,1>, cudaFuncAttributeMaxDynamicSharedMemorySize, SMEM3);
    cudaFuncSetAttribute(gemm2<2,1,0,1>, cudaFuncAttributeMaxDynamicSharedMemorySize, SMEM3);
    cudaFuncSetAttribute(gemm2<2,1,1,1>, cudaFuncAttributeMaxDynamicSharedMemorySize, SMEM3);
    cudaFuncSetAttribute(gemm2<1,2,0,0>, cudaFuncAttributeMaxDynamicSharedMemorySize, SMEM2);
    cudaFuncSetAttribute(gemm2<1,1,0,0>, cudaFuncAttributeMaxDynamicSharedMemorySize, SMEM2);
    cudaFuncSetAttribute(gemm2<2,0,1,1>, cudaFuncAttributeMaxDynamicSharedMemorySize, SMEM3);

    const long SD = (long)S_TOK * D_DIM;
    const long SS = (long)S_TOK * S_TOK;
    const long SC = (long)S_TOK * C_DIM;
    const long CS = (long)C_DIM * S_TOK;
    const float attn_scale = 0.044194173824159216f;   // 512^-0.5

    // ---- prep ----
    split_transpose_x<<<dim3(S_TOK / 32, C_DIM / 32, BATCH), 256>>>(x, xh, xl);
    split_mat<<<1024, 256>>>(Wq, Wqh, Wql, D_DIM * C_DIM);
    split_mat<<<1024, 256>>>(Wk, Wkh, Wkl, D_DIM * C_DIM);
    split_mat<<<1024, 256>>>(Wv, Wvh, Wvl, D_DIM * C_DIM);
    split_mat<<<1024, 256>>>(Wo, Woh, Wol, C_DIM * D_DIM);

    dim3 gProj(S_TOK / 256, D_DIM / 128, BATCH);   // (16, 4, 4)
    dim3 gSim (S_TOK / 256, S_TOK / 128, BATCH);   // (16, 32, 4)

    // ---- QKV projections (3-pass; attn scale folded into Q) ----
    gemm2<2,2,0,1><<<gProj, 256, SMEM3>>>(xh, xl, SC, C_DIM, Wqh, Wql, 0,
        nullptr, Q, nullptr, SD, D_DIM, bq, attn_scale);
    gemm2<2,1,0,1><<<gProj, 256, SMEM3>>>(xh, xl, SC, C_DIM, Wkh, Wkl, 0,
        nullptr, Kh, Kl, SD, D_DIM, bk, 1.f);
    gemm2<2,1,1,1><<<gProj, 256, SMEM3>>>(xh, xl, SC, C_DIM, Wvh, Wvl, 0,
        nullptr, Vth, Vtl, SD, S_TOK, bv, 1.f);

    // ---- sim = Q K^T (2-pass, fp16 out) ----
    gemm2<1,2,0,0><<<gSim, 256, SMEM2>>>(Q, nullptr, SD, D_DIM, Kh, Kl, SD,
        nullptr, P, nullptr, SS, S_TOK, nullptr, 1.f);

    // ---- softmax (in-place fp16) ----
    softmax_h<<<BATCH * S_TOK, 256>>>(P);

    // ---- O = attn @ V  (2-pass, split fp16 out) ----
    gemm2<1,1,0,0><<<gProj, 256, SMEM2>>>(P, nullptr, SS, S_TOK, Vth, Vtl, SD,
        nullptr, Oh, Ol, SD, D_DIM, nullptr, 1.f);

    // ---- y = O Wo^T + bo  (3-pass, fp32 transposed store) ----
    gemm2<2,0,1,1><<<gProj, 256, SMEM3>>>(Oh, Ol, SD, D_DIM, Woh, Wol, 0,
        out, nullptr, nullptr, CS, S_TOK, bo, 1.f);
}

// round 5
// speedup vs baseline: 4.4166x; 1.4557x over previous
#include <cuda_runtime.h>
#include <cuda_fp16.h>
#include <cstdint>

#define S_TOK 4096
#define C_DIM 512
#define D_DIM 512
#define BATCH 4

// ---------------------------------------------------------------------------
// Scratch (device globals; no allocations allowed)
// ---------------------------------------------------------------------------
__device__ __half g_xh[(size_t)BATCH * S_TOK * C_DIM];
__device__ __half g_Wqh[D_DIM * C_DIM], g_Wql[D_DIM * C_DIM];
__device__ __half g_Wkh[D_DIM * C_DIM], g_Wkl[D_DIM * C_DIM];
__device__ __half g_Wvh[D_DIM * C_DIM], g_Wvl[D_DIM * C_DIM];
__device__ __half g_Woh[C_DIM * D_DIM], g_Wol[C_DIM * D_DIM];
__device__ __half g_Q [(size_t)BATCH * S_TOK * D_DIM];   // scaled, fp16
__device__ __half g_K [(size_t)BATCH * S_TOK * D_DIM];   // fp16
__device__ __half g_Vt[(size_t)BATCH * D_DIM * S_TOK];   // V^T (d-major), fp16
__device__ __half g_P [(size_t)BATCH * S_TOK * S_TOK];   // 128 MB
__device__ __half g_Oh[(size_t)BATCH * S_TOK * D_DIM];
__device__ __half g_Ol[(size_t)BATCH * S_TOK * D_DIM];

// ---------------------------------------------------------------------------
// PTX helpers (sm_103-portable: mma.sync / ldmatrix / cp.async only)
// ---------------------------------------------------------------------------
__device__ __forceinline__ uint32_t smem_u32(const void* p) {
    uint32_t a;
    asm("{ .reg .u64 t; cvta.to.shared.u64 t, %1; cvt.u32.u64 %0, t; }"
        : "=r"(a) : "l"(p));
    return a;
}

#define CP16(dst, src) \
    asm volatile("cp.async.cg.shared.global [%0], [%1], 16;" \
                 :: "r"(dst), "l"(src) : "memory")
#define CP_COMMIT() asm volatile("cp.async.commit_group;" ::: "memory")
#define CP_WAIT(n)  asm volatile("cp.async.wait_group %0;" :: "n"(n) : "memory")

#define LDSM_X4(r, addr)                                                      \
    asm volatile("ldmatrix.sync.aligned.m8n8.x4.shared.b16 {%0,%1,%2,%3}, [%4];" \
                 : "=r"((r)[0]), "=r"((r)[1]), "=r"((r)[2]), "=r"((r)[3])     \
                 : "r"(addr))

#define MMA16816(d, a, b0, b1)                                                \
    asm volatile("mma.sync.aligned.m16n8k16.row.col.f32.f16.f16.f32 "        \
                 "{%0,%1,%2,%3}, {%4,%5,%6,%7}, {%8,%9}, {%0,%1,%2,%3};"     \
                 : "+f"((d)[0]), "+f"((d)[1]), "+f"((d)[2]), "+f"((d)[3])    \
                 : "r"((a)[0]), "r"((a)[1]), "r"((a)[2]), "r"((a)[3]),       \
                   "r"(b0), "r"(b1))

// One full 64x64x16 warp pass: 4 mi x 8 n8 MMAs
#define MMA_PASS(af, bf)                                                      \
    _Pragma("unroll")                                                         \
    for (int mi = 0; mi < 4; mi++) {                                          \
        _Pragma("unroll")                                                     \
        for (int ng = 0; ng < 4; ng++) {                                      \
            MMA16816(acc[mi][2 * ng],     (af)[mi], (bf)[ng][0], (bf)[ng][1]); \
            MMA16816(acc[mi][2 * ng + 1], (af)[mi], (bf)[ng][2], (bf)[ng][3]); \
        }                                                                     \
    }

// ---------------------------------------------------------------------------
// Split-fp16 mma.sync GEMM: C(M,N) = scale * (sum_k A(m,k)*B(n,k) + bias[n])
// A,B k-contiguous (lda = ldb = Ktot).
// APASS: 1 -> Ah*Bh                      (A,B single plane)
//        2 -> Ah*Bh + Ah*Bl              (B split hi/lo)
//        3 -> Ah*Bh + Al*Bh + Ah*Bl      (A and B split)
// OUTMODE: 0 = fp32, 1 = split fp16 (hi+lo), 2 = single fp16
// CTA tile 256(M) x 128(N), 8 warps of 64x64; K chunked by 32, double-buffered.
// Smem rows padded to 80B -> conflict-free ldmatrix.
// ---------------------------------------------------------------------------
template<int APASS, int OUTMODE, int TRANS, int HAS_BIAS>
__global__ __launch_bounds__(256)
void gemm3(const __half* __restrict__ Ah, const __half* __restrict__ Al,
           long aStride, int Ktot,
           const __half* __restrict__ Bh, const __half* __restrict__ Bl,
           long bStride,
           float* __restrict__ Cf, __half* __restrict__ Ch,
           __half* __restrict__ Cl, long cStride, int ldc,
           const float* __restrict__ bias, float scale)
{
    constexpr int AH_OFF = 0;
    constexpr int AL_OFF = 20480;                       // used only if APASS==3
    constexpr int BH_OFF = (APASS == 3) ? 40960 : 20480;
    constexpr int BL_OFF = BH_OFF + 10240;              // used only if APASS>=2
    constexpr int STAGE  = BH_OFF + ((APASS >= 2) ? 20480 : 10240);

    extern __shared__ char smch[];
    const uint32_t sbase = smem_u32(smch);

    const int tid  = threadIdx.x;
    const int lane = tid & 31;
    const int wid  = tid >> 5;
    const int m0 = blockIdx.x * 256;
    const int n0 = blockIdx.y * 128;
    const int bz = blockIdx.z;

    const __half* ArowH = Ah + (long)bz * aStride + (long)m0 * Ktot;
    const __half* ArowL = (APASS == 3) ? (Al + (long)bz * aStride + (long)m0 * Ktot) : ArowH;
    const __half* BrowH = Bh + (long)bz * bStride + (long)n0 * Ktot;
    const __half* BrowL = (APASS >= 2) ? (Bl + (long)bz * bStride + (long)n0 * Ktot) : BrowH;

    const int ldrow = tid >> 2;     // 0..63
    const int ldq   = tid & 3;      // 16B quarter of 64B row
    auto stage_load = [&](int c, int buf) {
        const long kof = (long)c << 5;
        const uint32_t s0 = sbase + buf * STAGE;
        #pragma unroll
        for (int i = 0; i < 4; i++) {                 // A: 256 rows
            const int row = ldrow + i * 64;
            const uint32_t doff = (uint32_t)(row * 80 + ldq * 16);
            const long goff = (long)row * Ktot + kof + ldq * 8;
            CP16(s0 + AH_OFF + doff, ArowH + goff);
            if (APASS == 3) CP16(s0 + AL_OFF + doff, ArowL + goff);
        }
        #pragma unroll
        for (int i = 0; i < 2; i++) {                 // B: 128 rows
            const int row = ldrow + i * 64;
            const uint32_t doff = (uint32_t)(row * 80 + ldq * 16);
            const long goff = (long)row * Ktot + kof + ldq * 8;
            CP16(s0 + BH_OFF + doff, BrowH + goff);
            if (APASS >= 2) CP16(s0 + BL_OFF + doff, BrowL + goff);
        }
    };

    float acc[4][8][4];
    #pragma unroll
    for (int i = 0; i < 4; i++)
        #pragma unroll
        for (int j = 0; j < 8; j++)
            #pragma unroll
            for (int q = 0; q < 4; q++) acc[i][j][q] = 0.f;

    // warp tile 64x64: 4 warps along M, 2 along N
    const int wr = wid & 3;
    const int wc = wid >> 2;

    const uint32_t aAddr0 = (uint32_t)((wr * 64 + (lane & 15)) * 80 + ((lane >> 4) << 4));
    const uint32_t bAddr0 = (uint32_t)((wc * 64 + ((lane >> 4) << 3) + (lane & 7)) * 80
                                       + (((lane >> 3) & 1) << 4));

    const int nCh = Ktot >> 5;
    stage_load(0, 0);
    CP_COMMIT();

    for (int c = 0; c < nCh; c++) {
        const int buf = c & 1;
        if (c + 1 < nCh) {
            stage_load(c + 1, buf ^ 1);
            CP_COMMIT();
            CP_WAIT(1);
        } else {
            CP_WAIT(0);
        }
        __syncthreads();

        const uint32_t s0 = sbase + buf * STAGE;
        #pragma unroll
        for (int k16 = 0; k16 < 2; k16++) {
            const uint32_t aA = s0 + AH_OFF + aAddr0 + k16 * 32;
            const uint32_t bA = s0 + BH_OFF + bAddr0 + k16 * 32;

            uint32_t ah[4][4], bb[4][4];
            #pragma unroll
            for (int mi = 0; mi < 4; mi++) LDSM_X4(ah[mi], aA + mi * 1280);
            #pragma unroll
            for (int ng = 0; ng < 4; ng++) LDSM_X4(bb[ng], bA + ng * 1280);

            MMA_PASS(ah, bb);                         // Ah * Bh

            if (APASS == 3) {
                uint32_t al[4][4];
                #pragma unroll
                for (int mi = 0; mi < 4; mi++)
                    LDSM_X4(al[mi], aA + (AL_OFF - AH_OFF) + mi * 1280);
                MMA_PASS(al, bb);                     // Al * Bh
            }
            if (APASS >= 2) {
                #pragma unroll
                for (int ng = 0; ng < 4; ng++)
                    LDSM_X4(bb[ng], bA + (BL_OFF - BH_OFF) + ng * 1280);
                MMA_PASS(ah, bb);                     // Ah * Bl
            }
        }
        __syncthreads();
    }

    // ---- epilogue ----
    const int tq = lane >> 2;
    const int tr = lane & 3;

    #pragma unroll
    for (int mi = 0; mi < 4; mi++) {
        #pragma unroll
        for (int n8 = 0; n8 < 8; n8++) {
            const int r  = m0 + wr * 64 + mi * 16 + tq;
            const int cc = n0 + wc * 64 + n8 * 8 + tr * 2;
            const float b0 = HAS_BIAS ? bias[cc]     : 0.f;
            const float b1 = HAS_BIAS ? bias[cc + 1] : 0.f;
            const float v00 = (acc[mi][n8][0] + b0) * scale;
            const float v01 = (acc[mi][n8][1] + b1) * scale;
            const float v10 = (acc[mi][n8][2] + b0) * scale;
            const float v11 = (acc[mi][n8][3] + b1) * scale;

            if (OUTMODE == 0) {
                float* base = Cf + (long)bz * cStride;
                if (TRANS == 0) {
                    *reinterpret_cast<float2*>(base + (long)r * ldc + cc)       = make_float2(v00, v01);
                    *reinterpret_cast<float2*>(base + (long)(r + 8) * ldc + cc) = make_float2(v10, v11);
                } else {
                    base[(long)cc * ldc + r]           = v00;
                    base[(long)(cc + 1) * ldc + r]     = v01;
                    base[(long)cc * ldc + r + 8]       = v10;
                    base[(long)(cc + 1) * ldc + r + 8] = v11;
                }
            } else if (OUTMODE == 2) {
                __half* base = Ch + (long)bz * cStride;
                if (TRANS == 0) {
                    *reinterpret_cast<__half2*>(base + (long)r * ldc + cc)       = __floats2half2_rn(v00, v01);
                    *reinterpret_cast<__half2*>(base + (long)(r + 8) * ldc + cc) = __floats2half2_rn(v10, v11);
                } else {
                    base[(long)cc * ldc + r]           = __float2half_rn(v00);
                    base[(long)(cc + 1) * ldc + r]     = __float2half_rn(v01);
                    base[(long)cc * ldc + r + 8]       = __float2half_rn(v10);
                    base[(long)(cc + 1) * ldc + r + 8] = __float2half_rn(v11);
                }
            } else {  // OUTMODE == 1: split fp16 (row-major only)
                __half* bH = Ch + (long)bz * cStride;
                __half* bL = Cl + (long)bz * cStride;
                __half h00 = __float2half_rn(v00), h01 = __float2half_rn(v01);
                __half h10 = __float2half_rn(v10), h11 = __float2half_rn(v11);
                __half l00 = __float2half_rn(v00 - __half2float(h00));
                __half l01 = __float2half_rn(v01 - __half2float(h01));
                __half l10 = __float2half_rn(v10 - __half2float(h10));
                __half l11 = __float2half_rn(v11 - __half2float(h11));
                *reinterpret_cast<__half2*>(bH + (long)r * ldc + cc)       = __halves2half2(h00, h01);
                *reinterpret_cast<__half2*>(bH + (long)(r + 8) * ldc + cc) = __halves2half2(h10, h11);
                *reinterpret_cast<__half2*>(bL + (long)r * ldc + cc)       = __halves2half2(l00, l01);
                *reinterpret_cast<__half2*>(bL + (long)(r + 8) * ldc + cc) = __halves2half2(l10, l11);
            }
        }
    }
}

// ---------------------------------------------------------------------------
// Prep: transpose x (B,C,S) fp32 -> xh (B,S,C) fp16
// ---------------------------------------------------------------------------
__global__ __launch_bounds__(256)
void transpose_x(const float* __restrict__ x, __half* __restrict__ xh)
{
    __shared__ float t[32][33];
    const int b = blockIdx.z;
    const int s0 = blockIdx.x << 5, c0 = blockIdx.y << 5;
    const float* xb = x + (long)b * C_DIM * S_TOK;
    const int a = threadIdx.x & 31, q8 = threadIdx.x >> 5;
    #pragma unroll
    for (int i = 0; i < 4; i++) {
        int cc = q8 + (i << 3);
        t[cc][a] = xb[(long)(c0 + cc) * S_TOK + s0 + a];
    }
    __syncthreads();
    const long ob = (long)b * S_TOK * C_DIM;
    #pragma unroll
    for (int i = 0; i < 4; i++) {
        int ss = q8 + (i << 3);
        xh[ob + (long)(s0 + ss) * C_DIM + c0 + a] = __float2half_rn(t[a][ss]);
    }
}

__global__ __launch_bounds__(256)
void split_mat(const float* __restrict__ w,
               __half* __restrict__ wh, __half* __restrict__ wl, int n)
{
    int i = blockIdx.x * 256 + threadIdx.x;
    if (i < n) {
        float v = w[i];
        __half h = __float2half_rn(v);
        wh[i] = h;
        wl[i] = __float2half_rn(v - __half2float(h));
    }
}

// ---------------------------------------------------------------------------
// In-place row softmax over 4096-wide fp16 rows (compute in fp32)
// ---------------------------------------------------------------------------
__global__ __launch_bounds__(256)
void softmax_h(__half* __restrict__ P)
{
    const long row = blockIdx.x;
    uint4* p4 = reinterpret_cast<uint4*>(P + row * S_TOK);   // 8 halves per uint4
    const int tid = threadIdx.x;

    uint4 raw[2];
    float v[16];
    #pragma unroll
    for (int i = 0; i < 2; i++) {
        raw[i] = p4[tid + (i << 8)];
        const __half2* h = reinterpret_cast<const __half2*>(&raw[i]);
        #pragma unroll
        for (int j = 0; j < 4; j++) {
            float2 f = __half22float2(h[j]);
            v[i * 8 + j * 2]     = f.x;
            v[i * 8 + j * 2 + 1] = f.y;
        }
    }

    float mx = -3.4e38f;
    #pragma unroll
    for (int j = 0; j < 16; j++) mx = fmaxf(mx, v[j]);

    __shared__ float red[8];
    #pragma unroll
    for (int o = 16; o > 0; o >>= 1)
        mx = fmaxf(mx, __shfl_xor_sync(0xffffffffu, mx, o));
    if ((tid & 31) == 0) red[tid >> 5] = mx;
    __syncthreads();
    float m = red[0];
    #pragma unroll
    for (int w = 1; w < 8; w++) m = fmaxf(m, red[w]);
    __syncthreads();

    float s = 0.f;
    #pragma unroll
    for (int j = 0; j < 16; j++) { v[j] = __expf(v[j] - m); s += v[j]; }
    #pragma unroll
    for (int o = 16; o > 0; o >>= 1)
        s += __shfl_xor_sync(0xffffffffu, s, o);
    if ((tid & 31) == 0) red[tid >> 5] = s;
    __syncthreads();
    float tot = red[0];
    #pragma unroll
    for (int w = 1; w < 8; w++) tot += red[w];
    const float inv = 1.0f / tot;

    #pragma unroll
    for (int i = 0; i < 2; i++) {
        uint4 outp;
        __half2* h = reinterpret_cast<__half2*>(&outp);
        #pragma unroll
        for (int j = 0; j < 4; j++)
            h[j] = __floats2half2_rn(v[i * 8 + j * 2] * inv, v[i * 8 + j * 2 + 1] * inv);
        p4[tid + (i << 8)] = outp;
    }
}

// ---------------------------------------------------------------------------
extern "C" void kernel_launch(void* const* d_in, const int* in_sizes, int n_in,
                              void* d_out, int out_size)
{
    const float* x  = (const float*)d_in[0];
    const float* Wq = (const float*)d_in[1];
    const float* bq = (const float*)d_in[2];
    const float* Wk = (const float*)d_in[3];
    const float* bk = (const float*)d_in[4];
    const float* Wv = (const float*)d_in[5];
    const float* bv = (const float*)d_in[6];
    const float* Wo = (const float*)d_in[7];
    const float* bo = (const float*)d_in[8];
    float* out = (float*)d_out;

    __half *xh, *Wqh, *Wql, *Wkh, *Wkl, *Wvh, *Wvl, *Woh, *Wol;
    __half *Q, *K, *Vt, *P, *Oh, *Ol;
    cudaGetSymbolAddress((void**)&xh, g_xh);
    cudaGetSymbolAddress((void**)&Wqh, g_Wqh); cudaGetSymbolAddress((void**)&Wql, g_Wql);
    cudaGetSymbolAddress((void**)&Wkh, g_Wkh); cudaGetSymbolAddress((void**)&Wkl, g_Wkl);
    cudaGetSymbolAddress((void**)&Wvh, g_Wvh); cudaGetSymbolAddress((void**)&Wvl, g_Wvl);
    cudaGetSymbolAddress((void**)&Woh, g_Woh); cudaGetSymbolAddress((void**)&Wol, g_Wol);
    cudaGetSymbolAddress((void**)&Q, g_Q);     cudaGetSymbolAddress((void**)&K, g_K);
    cudaGetSymbolAddress((void**)&Vt, g_Vt);   cudaGetSymbolAddress((void**)&P, g_P);
    cudaGetSymbolAddress((void**)&Oh, g_Oh);   cudaGetSymbolAddress((void**)&Ol, g_Ol);

    const int S1 = 2 * 30720;    // APASS==1
    const int S2 = 2 * 40960;    // APASS==2
    const int S3 = 2 * 61440;    // APASS==3
    cudaFuncSetAttribute(gemm3<2,2,0,1>, cudaFuncAttributeMaxDynamicSharedMemorySize, S2);
    cudaFuncSetAttribute(gemm3<2,2,1,1>, cudaFuncAttributeMaxDynamicSharedMemorySize, S2);
    cudaFuncSetAttribute(gemm3<1,2,0,0>, cudaFuncAttributeMaxDynamicSharedMemorySize, S1);
    cudaFuncSetAttribute(gemm3<1,1,0,0>, cudaFuncAttributeMaxDynamicSharedMemorySize, S1);
    cudaFuncSetAttribute(gemm3<3,0,1,1>, cudaFuncAttributeMaxDynamicSharedMemorySize, S3);

    const long SD = (long)S_TOK * D_DIM;
    const long SS = (long)S_TOK * S_TOK;
    const long SC = (long)S_TOK * C_DIM;
    const long CS = (long)C_DIM * S_TOK;
    const float attn_scale = 0.044194173824159216f;   // 512^-0.5

    // ---- prep ----
    transpose_x<<<dim3(S_TOK / 32, C_DIM / 32, BATCH), 256>>>(x, xh);
    split_mat<<<1024, 256>>>(Wq, Wqh, Wql, D_DIM * C_DIM);
    split_mat<<<1024, 256>>>(Wk, Wkh, Wkl, D_DIM * C_DIM);
    split_mat<<<1024, 256>>>(Wv, Wvh, Wvl, D_DIM * C_DIM);
    split_mat<<<1024, 256>>>(Wo, Woh, Wol, C_DIM * D_DIM);

    dim3 gProj(S_TOK / 256, D_DIM / 128, BATCH);   // (16, 4, 4)
    dim3 gSim (S_TOK / 256, S_TOK / 128, BATCH);   // (16, 32, 4)

    // ---- QKV projections (2-pass: x fp16, W split; attn scale folded into Q) ----
    gemm3<2,2,0,1><<<gProj, 256, S2>>>(xh, nullptr, SC, C_DIM, Wqh, Wql, 0,
        nullptr, Q, nullptr, SD, D_DIM, bq, attn_scale);
    gemm3<2,2,0,1><<<gProj, 256, S2>>>(xh, nullptr, SC, C_DIM, Wkh, Wkl, 0,
        nullptr, K, nullptr, SD, D_DIM, bk, 1.f);
    gemm3<2,2,1,1><<<gProj, 256, S2>>>(xh, nullptr, SC, C_DIM, Wvh, Wvl, 0,
        nullptr, Vt, nullptr, SD, S_TOK, bv, 1.f);

    // ---- sim = Q K^T (1-pass, fp16 out) ----
    gemm3<1,2,0,0><<<gSim, 256, S1>>>(Q, nullptr, SD, D_DIM, K, nullptr, SD,
        nullptr, P, nullptr, SS, S_TOK, nullptr, 1.f);

    // ---- softmax (in-place fp16) ----
    softmax_h<<<BATCH * S_TOK, 256>>>(P);

    // ---- O = attn @ V  (1-pass, split fp16 out) ----
    gemm3<1,1,0,0><<<gProj, 256, S1>>>(P, nullptr, SS, S_TOK, Vt, nullptr, SD,
        nullptr, Oh, Ol, SD, D_DIM, nullptr, 1.f);

    // ---- y = O Wo^T + bo  (3-pass, fp32 transposed store) ----
    gemm3<3,0,1,1><<<gProj, 256, S3>>>(Oh, Ol, SD, D_DIM, Woh, Wol, 0,
        out, nullptr, nullptr, CS, S_TOK, bo, 1.f);
}

// round 6
// speedup vs baseline: 4.8589x; 1.1002x over previous
#include <cuda_runtime.h>
#include <cuda_fp16.h>
#include <cstdint>

#define S_TOK 4096
#define C_DIM 512
#define D_DIM 512
#define BATCH 4

// ---------------------------------------------------------------------------
// Scratch (device globals; no allocations allowed)
// ---------------------------------------------------------------------------
__device__ __half g_xh[(size_t)BATCH * S_TOK * C_DIM];
__device__ __half g_Wq[D_DIM * C_DIM];
__device__ __half g_Wk[D_DIM * C_DIM];
__device__ __half g_Wv[D_DIM * C_DIM];
__device__ __half g_Woh[C_DIM * D_DIM], g_Wol[C_DIM * D_DIM];
__device__ __half g_Q [(size_t)BATCH * S_TOK * D_DIM];   // scaled, fp16
__device__ __half g_K [(size_t)BATCH * S_TOK * D_DIM];   // fp16
__device__ __half g_Vt[(size_t)BATCH * D_DIM * S_TOK];   // V^T (d-major), fp16
__device__ __half g_P [(size_t)BATCH * S_TOK * S_TOK];   // 128 MB
__device__ __half g_O [(size_t)BATCH * S_TOK * D_DIM];   // fp16

// ---------------------------------------------------------------------------
// PTX helpers (sm_103-portable: mma.sync / ldmatrix / cp.async only)
// ---------------------------------------------------------------------------
__device__ __forceinline__ uint32_t smem_u32(const void* p) {
    uint32_t a;
    asm("{ .reg .u64 t; cvta.to.shared.u64 t, %1; cvt.u32.u64 %0, t; }"
        : "=r"(a) : "l"(p));
    return a;
}

#define CP16(dst, src) \
    asm volatile("cp.async.cg.shared.global [%0], [%1], 16;" \
                 :: "r"(dst), "l"(src) : "memory")
#define CP_COMMIT() asm volatile("cp.async.commit_group;" ::: "memory")
#define CP_WAIT(n)  asm volatile("cp.async.wait_group %0;" :: "n"(n) : "memory")

#define LDSM_X4(r, addr)                                                      \
    asm volatile("ldmatrix.sync.aligned.m8n8.x4.shared.b16 {%0,%1,%2,%3}, [%4];" \
                 : "=r"((r)[0]), "=r"((r)[1]), "=r"((r)[2]), "=r"((r)[3])     \
                 : "r"(addr))

#define MMA16816(d, a, b0, b1)                                                \
    asm volatile("mma.sync.aligned.m16n8k16.row.col.f32.f16.f16.f32 "        \
                 "{%0,%1,%2,%3}, {%4,%5,%6,%7}, {%8,%9}, {%0,%1,%2,%3};"     \
                 : "+f"((d)[0]), "+f"((d)[1]), "+f"((d)[2]), "+f"((d)[3])    \
                 : "r"((a)[0]), "r"((a)[1]), "r"((a)[2]), "r"((a)[3]),       \
                   "r"(b0), "r"(b1))

// One full 64x64x16 warp pass: 4 mi x 8 n8 MMAs
#define MMA_PASS(af, bf)                                                      \
    _Pragma("unroll")                                                         \
    for (int mi = 0; mi < 4; mi++) {                                          \
        _Pragma("unroll")                                                     \
        for (int ng = 0; ng < 4; ng++) {                                      \
            MMA16816(acc[mi][2 * ng],     (af)[mi], (bf)[ng][0], (bf)[ng][1]); \
            MMA16816(acc[mi][2 * ng + 1], (af)[mi], (bf)[ng][2], (bf)[ng][3]); \
        }                                                                     \
    }

// ---------------------------------------------------------------------------
// Split-fp16 mma.sync GEMM: C(M,N) = scale * (sum_k A(m,k)*B(n,k) + bias[n])
// A,B k-contiguous (lda = ldb = Ktot).
// APASS: 1 -> Ah*Bh              (A,B single plane)
//        2 -> Ah*Bh + Ah*Bl      (B split hi/lo)
// OUTMODE: 0 = fp32, 2 = single fp16
// CTA tile 256(M) x 128(N), 8 warps of 64x64; K chunked by 32, 3-stage pipeline.
// Smem rows padded to 80B -> conflict-free ldmatrix.
// ---------------------------------------------------------------------------
template<int APASS, int OUTMODE, int TRANS, int HAS_BIAS>
__global__ __launch_bounds__(256)
void gemm3(const __half* __restrict__ Ah, long aStride, int Ktot,
           const __half* __restrict__ Bh, const __half* __restrict__ Bl,
           long bStride,
           float* __restrict__ Cf, __half* __restrict__ Ch,
           long cStride, int ldc,
           const float* __restrict__ bias, float scale)
{
    constexpr int AH_OFF = 0;
    constexpr int BH_OFF = 20480;
    constexpr int BL_OFF = 30720;                         // used only if APASS==2
    constexpr int STAGE  = (APASS == 2) ? 40960 : 30720;
    constexpr int NSTAGE = 3;

    extern __shared__ char smch[];
    const uint32_t sbase = smem_u32(smch);

    const int tid  = threadIdx.x;
    const int lane = tid & 31;
    const int wid  = tid >> 5;
    const int m0 = blockIdx.x * 256;
    const int n0 = blockIdx.y * 128;
    const int bz = blockIdx.z;

    const __half* ArowH = Ah + (long)bz * aStride + (long)m0 * Ktot;
    const __half* BrowH = Bh + (long)bz * bStride + (long)n0 * Ktot;
    const __half* BrowL = (APASS == 2) ? (Bl + (long)bz * bStride + (long)n0 * Ktot) : BrowH;

    const int ldrow = tid >> 2;     // 0..63
    const int ldq   = tid & 3;      // 16B quarter of 64B row
    auto stage_load = [&](int c, int buf) {
        const long kof = (long)c << 5;
        const uint32_t s0 = sbase + buf * STAGE;
        #pragma unroll
        for (int i = 0; i < 4; i++) {                 // A: 256 rows
            const int row = ldrow + i * 64;
            const uint32_t doff = (uint32_t)(row * 80 + ldq * 16);
            const long goff = (long)row * Ktot + kof + ldq * 8;
            CP16(s0 + AH_OFF + doff, ArowH + goff);
        }
        #pragma unroll
        for (int i = 0; i < 2; i++) {                 // B: 128 rows
            const int row = ldrow + i * 64;
            const uint32_t doff = (uint32_t)(row * 80 + ldq * 16);
            const long goff = (long)row * Ktot + kof + ldq * 8;
            CP16(s0 + BH_OFF + doff, BrowH + goff);
            if (APASS == 2) CP16(s0 + BL_OFF + doff, BrowL + goff);
        }
    };

    float acc[4][8][4];
    #pragma unroll
    for (int i = 0; i < 4; i++)
        #pragma unroll
        for (int j = 0; j < 8; j++)
            #pragma unroll
            for (int q = 0; q < 4; q++) acc[i][j][q] = 0.f;

    // warp tile 64x64: 4 warps along M, 2 along N
    const int wr = wid & 3;
    const int wc = wid >> 2;

    const uint32_t aAddr0 = (uint32_t)((wr * 64 + (lane & 15)) * 80 + ((lane >> 4) << 4));
    const uint32_t bAddr0 = (uint32_t)((wc * 64 + ((lane >> 4) << 3) + (lane & 7)) * 80
                                       + (((lane >> 3) & 1) << 4));

    const int nCh = Ktot >> 5;

    // prologue: fill NSTAGE-1 stages
    stage_load(0, 0);
    CP_COMMIT();
    if (nCh > 1) stage_load(1, 1);
    CP_COMMIT();

    int bufc = 0;                       // buffer index of chunk c
    for (int c = 0; c < nCh; c++) {
        // issue load of chunk c+2 into the buffer freed after iteration c-1
        if (c + 2 < nCh) {
            int b2 = bufc + 2; if (b2 >= NSTAGE) b2 -= NSTAGE;
            stage_load(c + 2, b2);
        }
        CP_COMMIT();
        CP_WAIT(2);                     // chunk c's group fully landed
        __syncthreads();

        const uint32_t s0 = sbase + bufc * STAGE;
        #pragma unroll
        for (int k16 = 0; k16 < 2; k16++) {
            const uint32_t aA = s0 + AH_OFF + aAddr0 + k16 * 32;
            const uint32_t bA = s0 + BH_OFF + bAddr0 + k16 * 32;

            uint32_t ah[4][4], bb[4][4];
            #pragma unroll
            for (int mi = 0; mi < 4; mi++) LDSM_X4(ah[mi], aA + mi * 1280);
            #pragma unroll
            for (int ng = 0; ng < 4; ng++) LDSM_X4(bb[ng], bA + ng * 1280);

            MMA_PASS(ah, bb);                         // Ah * Bh

            if (APASS == 2) {
                #pragma unroll
                for (int ng = 0; ng < 4; ng++)
                    LDSM_X4(bb[ng], bA + (BL_OFF - BH_OFF) + ng * 1280);
                MMA_PASS(ah, bb);                     // Ah * Bl
            }
        }
        __syncthreads();                // free bufc for the c+2 prefetch next iter
        if (++bufc == NSTAGE) bufc = 0;
    }

    // ---- epilogue ----
    const int tq = lane >> 2;
    const int tr = lane & 3;

    #pragma unroll
    for (int mi = 0; mi < 4; mi++) {
        #pragma unroll
        for (int n8 = 0; n8 < 8; n8++) {
            const int r  = m0 + wr * 64 + mi * 16 + tq;
            const int cc = n0 + wc * 64 + n8 * 8 + tr * 2;
            const float b0 = HAS_BIAS ? bias[cc]     : 0.f;
            const float b1 = HAS_BIAS ? bias[cc + 1] : 0.f;
            const float v00 = (acc[mi][n8][0] + b0) * scale;
            const float v01 = (acc[mi][n8][1] + b1) * scale;
            const float v10 = (acc[mi][n8][2] + b0) * scale;
            const float v11 = (acc[mi][n8][3] + b1) * scale;

            if (OUTMODE == 0) {
                float* base = Cf + (long)bz * cStride;
                if (TRANS == 0) {
                    *reinterpret_cast<float2*>(base + (long)r * ldc + cc)       = make_float2(v00, v01);
                    *reinterpret_cast<float2*>(base + (long)(r + 8) * ldc + cc) = make_float2(v10, v11);
                } else {
                    base[(long)cc * ldc + r]           = v00;
                    base[(long)(cc + 1) * ldc + r]     = v01;
                    base[(long)cc * ldc + r + 8]       = v10;
                    base[(long)(cc + 1) * ldc + r + 8] = v11;
                }
            } else {
                __half* base = Ch + (long)bz * cStride;
                if (TRANS == 0) {
                    *reinterpret_cast<__half2*>(base + (long)r * ldc + cc)       = __floats2half2_rn(v00, v01);
                    *reinterpret_cast<__half2*>(base + (long)(r + 8) * ldc + cc) = __floats2half2_rn(v10, v11);
                } else {
                    base[(long)cc * ldc + r]           = __float2half_rn(v00);
                    base[(long)(cc + 1) * ldc + r]     = __float2half_rn(v01);
                    base[(long)cc * ldc + r + 8]       = __float2half_rn(v10);
                    base[(long)(cc + 1) * ldc + r + 8] = __float2half_rn(v11);
                }
            }
        }
    }
}

// ---------------------------------------------------------------------------
// Prep: transpose x (B,C,S) fp32 -> xh (B,S,C) fp16
// ---------------------------------------------------------------------------
__global__ __launch_bounds__(256)
void transpose_x(const float* __restrict__ x, __half* __restrict__ xh)
{
    __shared__ float t[32][33];
    const int b = blockIdx.z;
    const int s0 = blockIdx.x << 5, c0 = blockIdx.y << 5;
    const float* xb = x + (long)b * C_DIM * S_TOK;
    const int a = threadIdx.x & 31, q8 = threadIdx.x >> 5;
    #pragma unroll
    for (int i = 0; i < 4; i++) {
        int cc = q8 + (i << 3);
        t[cc][a] = xb[(long)(c0 + cc) * S_TOK + s0 + a];
    }
    __syncthreads();
    const long ob = (long)b * S_TOK * C_DIM;
    #pragma unroll
    for (int i = 0; i < 4; i++) {
        int ss = q8 + (i << 3);
        xh[ob + (long)(s0 + ss) * C_DIM + c0 + a] = __float2half_rn(t[a][ss]);
    }
}

// Plain fp32 -> fp16 convert (for Wq, Wk, Wv)
__global__ __launch_bounds__(256)
void conv_mat(const float* __restrict__ w, __half* __restrict__ wh, int n)
{
    int i = blockIdx.x * 256 + threadIdx.x;
    if (i < n) wh[i] = __float2half_rn(w[i]);
}

// Split fp32 -> hi/lo fp16 (for Wo)
__global__ __launch_bounds__(256)
void split_mat(const float* __restrict__ w,
               __half* __restrict__ wh, __half* __restrict__ wl, int n)
{
    int i = blockIdx.x * 256 + threadIdx.x;
    if (i < n) {
        float v = w[i];
        __half h = __float2half_rn(v);
        wh[i] = h;
        wl[i] = __float2half_rn(v - __half2float(h));
    }
}

// ---------------------------------------------------------------------------
// In-place row softmax over 4096-wide fp16 rows (compute in fp32)
// ---------------------------------------------------------------------------
__global__ __launch_bounds__(256)
void softmax_h(__half* __restrict__ P)
{
    const long row = blockIdx.x;
    uint4* p4 = reinterpret_cast<uint4*>(P + row * S_TOK);   // 8 halves per uint4
    const int tid = threadIdx.x;

    uint4 raw[2];
    float v[16];
    #pragma unroll
    for (int i = 0; i < 2; i++) {
        raw[i] = p4[tid + (i << 8)];
        const __half2* h = reinterpret_cast<const __half2*>(&raw[i]);
        #pragma unroll
        for (int j = 0; j < 4; j++) {
            float2 f = __half22float2(h[j]);
            v[i * 8 + j * 2]     = f.x;
            v[i * 8 + j * 2 + 1] = f.y;
        }
    }

    float mx = -3.4e38f;
    #pragma unroll
    for (int j = 0; j < 16; j++) mx = fmaxf(mx, v[j]);

    __shared__ float red[8];
    #pragma unroll
    for (int o = 16; o > 0; o >>= 1)
        mx = fmaxf(mx, __shfl_xor_sync(0xffffffffu, mx, o));
    if ((tid & 31) == 0) red[tid >> 5] = mx;
    __syncthreads();
    float m = red[0];
    #pragma unroll
    for (int w = 1; w < 8; w++) m = fmaxf(m, red[w]);
    __syncthreads();

    float s = 0.f;
    #pragma unroll
    for (int j = 0; j < 16; j++) { v[j] = __expf(v[j] - m); s += v[j]; }
    #pragma unroll
    for (int o = 16; o > 0; o >>= 1)
        s += __shfl_xor_sync(0xffffffffu, s, o);
    if ((tid & 31) == 0) red[tid >> 5] = s;
    __syncthreads();
    float tot = red[0];
    #pragma unroll
    for (int w = 1; w < 8; w++) tot += red[w];
    const float inv = 1.0f / tot;

    #pragma unroll
    for (int i = 0; i < 2; i++) {
        uint4 outp;
        __half2* h = reinterpret_cast<__half2*>(&outp);
        #pragma unroll
        for (int j = 0; j < 4; j++)
            h[j] = __floats2half2_rn(v[i * 8 + j * 2] * inv, v[i * 8 + j * 2 + 1] * inv);
        p4[tid + (i << 8)] = outp;
    }
}

// ---------------------------------------------------------------------------
extern "C" void kernel_launch(void* const* d_in, const int* in_sizes, int n_in,
                              void* d_out, int out_size)
{
    const float* x  = (const float*)d_in[0];
    const float* Wq = (const float*)d_in[1];
    const float* bq = (const float*)d_in[2];
    const float* Wk = (const float*)d_in[3];
    const float* bk = (const float*)d_in[4];
    const float* Wv = (const float*)d_in[5];
    const float* bv = (const float*)d_in[6];
    const float* Wo = (const float*)d_in[7];
    const float* bo = (const float*)d_in[8];
    float* out = (float*)d_out;

    __half *xh, *Wqh, *Wkh, *Wvh, *Woh, *Wol;
    __half *Q, *K, *Vt, *P, *O;
    cudaGetSymbolAddress((void**)&xh, g_xh);
    cudaGetSymbolAddress((void**)&Wqh, g_Wq);
    cudaGetSymbolAddress((void**)&Wkh, g_Wk);
    cudaGetSymbolAddress((void**)&Wvh, g_Wv);
    cudaGetSymbolAddress((void**)&Woh, g_Woh); cudaGetSymbolAddress((void**)&Wol, g_Wol);
    cudaGetSymbolAddress((void**)&Q, g_Q);     cudaGetSymbolAddress((void**)&K, g_K);
    cudaGetSymbolAddress((void**)&Vt, g_Vt);   cudaGetSymbolAddress((void**)&P, g_P);
    cudaGetSymbolAddress((void**)&O, g_O);

    const int S1 = 3 * 30720;    // APASS==1, 3 stages
    const int S2 = 3 * 40960;    // APASS==2, 3 stages
    cudaFuncSetAttribute(gemm3<1,2,0,1>, cudaFuncAttributeMaxDynamicSharedMemorySize, S1);
    cudaFuncSetAttribute(gemm3<1,2,1,1>, cudaFuncAttributeMaxDynamicSharedMemorySize, S1);
    cudaFuncSetAttribute(gemm3<1,2,0,0>, cudaFuncAttributeMaxDynamicSharedMemorySize, S1);
    cudaFuncSetAttribute(gemm3<2,0,1,1>, cudaFuncAttributeMaxDynamicSharedMemorySize, S2);

    const long SD = (long)S_TOK * D_DIM;
    const long SS = (long)S_TOK * S_TOK;
    const long SC = (long)S_TOK * C_DIM;
    const long CS = (long)C_DIM * S_TOK;
    const float attn_scale = 0.044194173824159216f;   // 512^-0.5

    // ---- prep ----
    transpose_x<<<dim3(S_TOK / 32, C_DIM / 32, BATCH), 256>>>(x, xh);
    conv_mat<<<1024, 256>>>(Wq, Wqh, D_DIM * C_DIM);
    conv_mat<<<1024, 256>>>(Wk, Wkh, D_DIM * C_DIM);
    conv_mat<<<1024, 256>>>(Wv, Wvh, D_DIM * C_DIM);
    split_mat<<<1024, 256>>>(Wo, Woh, Wol, C_DIM * D_DIM);

    dim3 gProj(S_TOK / 256, D_DIM / 128, BATCH);   // (16, 4, 4)
    dim3 gSim (S_TOK / 256, S_TOK / 128, BATCH);   // (16, 32, 4)

    // ---- QKV projections (1-pass fp16; attn scale folded into Q) ----
    gemm3<1,2,0,1><<<gProj, 256, S1>>>(xh, SC, C_DIM, Wqh, nullptr, 0,
        nullptr, Q, SD, D_DIM, bq, attn_scale);
    gemm3<1,2,0,1><<<gProj, 256, S1>>>(xh, SC, C_DIM, Wkh, nullptr, 0,
        nullptr, K, SD, D_DIM, bk, 1.f);
    gemm3<1,2,1,1><<<gProj, 256, S1>>>(xh, SC, C_DIM, Wvh, nullptr, 0,
        nullptr, Vt, SD, S_TOK, bv, 1.f);

    // ---- sim = Q K^T (1-pass, fp16 out) ----
    gemm3<1,2,0,0><<<gSim, 256, S1>>>(Q, SD, D_DIM, K, nullptr, SD,
        nullptr, P, SS, S_TOK, nullptr, 1.f);

    // ---- softmax (in-place fp16) ----
    softmax_h<<<BATCH * S_TOK, 256>>>(P);

    // ---- O = attn @ V  (1-pass, fp16 out) ----
    gemm3<1,2,0,0><<<gProj, 256, S1>>>(P, SS, S_TOK, Vt, nullptr, SD,
        nullptr, O, SD, D_DIM, nullptr, 1.f);

    // ---- y = O Wo^T + bo  (2-pass, fp32 transposed store) ----
    gemm3<2,0,1,1><<<gProj, 256, S2>>>(O, SD, D_DIM, Woh, Wol, 0,
        out, nullptr, CS, S_TOK, bo, 1.f);
}

// round 7
// speedup vs baseline: 5.6624x; 1.1654x over previous
#include <cuda_runtime.h>
#include <cuda_fp16.h>
#include <cstdint>

#define S_TOK 4096
#define C_DIM 512
#define D_DIM 512
#define BATCH 4
#define NQKV  1536

// ---------------------------------------------------------------------------
// Scratch (device globals; no allocations allowed)
// ---------------------------------------------------------------------------
__device__ __half g_xh[(size_t)BATCH * S_TOK * C_DIM];
__device__ __half g_Wqkv[NQKV * C_DIM];                  // rows: Wq | Wk | Wv
__device__ float  g_bqkv[NQKV];
__device__ __half g_Woh[C_DIM * D_DIM], g_Wol[C_DIM * D_DIM];
__device__ __half g_QKV[(size_t)BATCH * S_TOK * NQKV];   // cols: Q(scaled) | K
__device__ __half g_Vt[(size_t)BATCH * D_DIM * S_TOK];   // V^T (d-major)
__device__ __half g_P [(size_t)BATCH * S_TOK * S_TOK];   // exp(logits), fp16
__device__ float  g_InvS[(size_t)BATCH * S_TOK];         // 1 / row sums
__device__ __half g_O [(size_t)BATCH * S_TOK * D_DIM];

// ---------------------------------------------------------------------------
// PTX helpers (sm_103-portable: mma.sync / ldmatrix / cp.async only)
// ---------------------------------------------------------------------------
__device__ __forceinline__ uint32_t smem_u32(const void* p) {
    uint32_t a;
    asm("{ .reg .u64 t; cvta.to.shared.u64 t, %1; cvt.u32.u64 %0, t; }"
        : "=r"(a) : "l"(p));
    return a;
}

#define CP16(dst, src) \
    asm volatile("cp.async.cg.shared.global [%0], [%1], 16;" \
                 :: "r"(dst), "l"(src) : "memory")
#define CP_COMMIT() asm volatile("cp.async.commit_group;" ::: "memory")
#define CP_WAIT(n)  asm volatile("cp.async.wait_group %0;" :: "n"(n) : "memory")

#define LDSM_X4(r, addr)                                                      \
    asm volatile("ldmatrix.sync.aligned.m8n8.x4.shared.b16 {%0,%1,%2,%3}, [%4];" \
                 : "=r"((r)[0]), "=r"((r)[1]), "=r"((r)[2]), "=r"((r)[3])     \
                 : "r"(addr))

#define MMA16816(d, a, b0, b1)                                                \
    asm volatile("mma.sync.aligned.m16n8k16.row.col.f32.f16.f16.f32 "        \
                 "{%0,%1,%2,%3}, {%4,%5,%6,%7}, {%8,%9}, {%0,%1,%2,%3};"     \
                 : "+f"((d)[0]), "+f"((d)[1]), "+f"((d)[2]), "+f"((d)[3])    \
                 : "r"((a)[0]), "r"((a)[1]), "r"((a)[2]), "r"((a)[3]),       \
                   "r"(b0), "r"(b1))

#define MMA_PASS(af, bf)                                                      \
    _Pragma("unroll")                                                         \
    for (int mi = 0; mi < 4; mi++) {                                          \
        _Pragma("unroll")                                                     \
        for (int ng = 0; ng < 4; ng++) {                                      \
            MMA16816(acc[mi][2 * ng],     (af)[mi], (bf)[ng][0], (bf)[ng][1]); \
            MMA16816(acc[mi][2 * ng + 1], (af)[mi], (bf)[ng][2], (bf)[ng][3]); \
        }                                                                     \
    }

// ---------------------------------------------------------------------------
// fp16 mma.sync GEMM: acc(M,N) = sum_k A(m,k)*B(n,k); epilogue per OUTMODE.
// A,B k-contiguous with leading dims lda/ldb.
// APASS: 1 -> Ah*Bh ; 2 -> Ah*Bh + Ah*Bl (B split hi/lo)
// OUTMODE 0: fp32 transposed store, (acc+bias)*scale          (out-proj)
//         1: fp16 row store of exp(acc)                       (sim)
//         2: fp16 row store of acc * rowscale[row]            (PV)
//         3: QKV dispatch: n<1024 row fp16 (acc+bias)*(n<512?scale:1),
//            n>=1024 transposed fp16 to Ch2 (V^T)             (QKV proj)
// CTA 256(M) x 128(N), 8 warps of 64x64; K chunk 32; 3-stage, 1 bar/chunk.
// ---------------------------------------------------------------------------
template<int APASS, int OUTMODE>
__global__ __launch_bounds__(256)
void gemm(const __half* __restrict__ Ah, int lda, long aStride, int Ktot,
          const __half* __restrict__ Bh, const __half* __restrict__ Bl,
          int ldb, long bStride,
          float* __restrict__ Cf, __half* __restrict__ Ch,
          __half* __restrict__ Ch2, long cStride, long c2Stride, int ldc,
          const float* __restrict__ bias, const float* __restrict__ rowscale,
          float scale)
{
    constexpr int AH_OFF = 0;
    constexpr int BH_OFF = 20480;
    constexpr int BL_OFF = 30720;                       // APASS==2 only
    constexpr int STAGE  = (APASS == 2) ? 40960 : 30720;
    constexpr int NSTAGE = 3;

    extern __shared__ char smch[];
    const uint32_t sbase = smem_u32(smch);

    const int tid  = threadIdx.x;
    const int lane = tid & 31;
    const int wid  = tid >> 5;
    const int m0 = blockIdx.x * 256;
    const int n0 = blockIdx.y * 128;
    const int bz = blockIdx.z;

    const __half* ArowH = Ah + (long)bz * aStride + (long)m0 * lda;
    const __half* BrowH = Bh + (long)bz * bStride + (long)n0 * ldb;
    const __half* BrowL = (APASS == 2) ? (Bl + (long)bz * bStride + (long)n0 * ldb) : BrowH;

    const int ldrow = tid >> 2;     // 0..63
    const int ldq   = tid & 3;      // 16B quarter of 64B row
    auto stage_load = [&](int c, int buf) {
        const long kof = (long)c << 5;
        const uint32_t s0 = sbase + buf * STAGE;
        #pragma unroll
        for (int i = 0; i < 4; i++) {                 // A: 256 rows
            const int row = ldrow + i * 64;
            const uint32_t doff = (uint32_t)(row * 80 + ldq * 16);
            const long goff = (long)row * lda + kof + ldq * 8;
            CP16(s0 + AH_OFF + doff, ArowH + goff);
        }
        #pragma unroll
        for (int i = 0; i < 2; i++) {                 // B: 128 rows
            const int row = ldrow + i * 64;
            const uint32_t doff = (uint32_t)(row * 80 + ldq * 16);
            const long goff = (long)row * ldb + kof + ldq * 8;
            CP16(s0 + BH_OFF + doff, BrowH + goff);
            if (APASS == 2) CP16(s0 + BL_OFF + doff, BrowL + goff);
        }
    };

    float acc[4][8][4];
    #pragma unroll
    for (int i = 0; i < 4; i++)
        #pragma unroll
        for (int j = 0; j < 8; j++)
            #pragma unroll
            for (int q = 0; q < 4; q++) acc[i][j][q] = 0.f;

    const int wr = wid & 3;         // warp tile 64x64: 4 along M, 2 along N
    const int wc = wid >> 2;

    const uint32_t aAddr0 = (uint32_t)((wr * 64 + (lane & 15)) * 80 + ((lane >> 4) << 4));
    const uint32_t bAddr0 = (uint32_t)((wc * 64 + ((lane >> 4) << 3) + (lane & 7)) * 80
                                       + (((lane >> 3) & 1) << 4));

    const int nCh = Ktot >> 5;

    stage_load(0, 0); CP_COMMIT();
    stage_load(1, 1); CP_COMMIT();

    int bufc = 0;
    for (int c = 0; c < nCh; c++) {
        if (c + 1 < nCh) { CP_WAIT(1); } else { CP_WAIT(0); }
        __syncthreads();            // single barrier: chunk c visible to all;
                                    // all warps done reading buffer (bufc+2)%3
        const uint32_t s0 = sbase + bufc * STAGE;
        #pragma unroll
        for (int k16 = 0; k16 < 2; k16++) {
            const uint32_t aA = s0 + AH_OFF + aAddr0 + k16 * 32;
            const uint32_t bA = s0 + BH_OFF + bAddr0 + k16 * 32;

            uint32_t ah[4][4], bb[4][4];
            #pragma unroll
            for (int mi = 0; mi < 4; mi++) LDSM_X4(ah[mi], aA + mi * 1280);
            #pragma unroll
            for (int ng = 0; ng < 4; ng++) LDSM_X4(bb[ng], bA + ng * 1280);

            MMA_PASS(ah, bb);                         // Ah * Bh

            if (APASS == 2) {
                #pragma unroll
                for (int ng = 0; ng < 4; ng++)
                    LDSM_X4(bb[ng], bA + (BL_OFF - BH_OFF) + ng * 1280);
                MMA_PASS(ah, bb);                     // Ah * Bl
            }
        }
        if (c + 2 < nCh) {
            int b2 = bufc + 2; if (b2 >= NSTAGE) b2 -= NSTAGE;
            stage_load(c + 2, b2);
        }
        CP_COMMIT();
        if (++bufc == NSTAGE) bufc = 0;
    }

    // ---- epilogue ----
    const int tq = lane >> 2;
    const int tr = lane & 3;

    #pragma unroll
    for (int mi = 0; mi < 4; mi++) {
        const int r = m0 + wr * 64 + mi * 16 + tq;
        float inv0 = 1.f, inv1 = 1.f;
        if (OUTMODE == 2) {
            inv0 = rowscale[(long)bz * S_TOK + r];
            inv1 = rowscale[(long)bz * S_TOK + r + 8];
        }
        #pragma unroll
        for (int n8 = 0; n8 < 8; n8++) {
            const int cc = n0 + wc * 64 + n8 * 8 + tr * 2;

            if (OUTMODE == 0) {            // fp32 transposed + bias
                const float b0 = bias[cc], b1 = bias[cc + 1];
                float* base = Cf + (long)bz * cStride;
                base[(long)cc * ldc + r]           = (acc[mi][n8][0] + b0) * scale;
                base[(long)(cc + 1) * ldc + r]     = (acc[mi][n8][1] + b1) * scale;
                base[(long)cc * ldc + r + 8]       = (acc[mi][n8][2] + b0) * scale;
                base[(long)(cc + 1) * ldc + r + 8] = (acc[mi][n8][3] + b1) * scale;
            } else if (OUTMODE == 1) {     // exp, fp16 row
                __half* base = Ch + (long)bz * cStride;
                *reinterpret_cast<__half2*>(base + (long)r * ldc + cc) =
                    __floats2half2_rn(__expf(acc[mi][n8][0]), __expf(acc[mi][n8][1]));
                *reinterpret_cast<__half2*>(base + (long)(r + 8) * ldc + cc) =
                    __floats2half2_rn(__expf(acc[mi][n8][2]), __expf(acc[mi][n8][3]));
            } else if (OUTMODE == 2) {     // row-scaled, fp16 row
                __half* base = Ch + (long)bz * cStride;
                *reinterpret_cast<__half2*>(base + (long)r * ldc + cc) =
                    __floats2half2_rn(acc[mi][n8][0] * inv0, acc[mi][n8][1] * inv0);
                *reinterpret_cast<__half2*>(base + (long)(r + 8) * ldc + cc) =
                    __floats2half2_rn(acc[mi][n8][2] * inv1, acc[mi][n8][3] * inv1);
            } else {                       // OUTMODE 3: QKV dispatch
                const float b0 = bias[cc], b1 = bias[cc + 1];
                const float sc = (n0 < 512) ? scale : 1.f;
                const float v00 = (acc[mi][n8][0] + b0) * sc;
                const float v01 = (acc[mi][n8][1] + b1) * sc;
                const float v10 = (acc[mi][n8][2] + b0) * sc;
                const float v11 = (acc[mi][n8][3] + b1) * sc;
                if (n0 < 1024) {           // Q | K: row-major into QKV
                    __half* base = Ch + (long)bz * cStride;
                    *reinterpret_cast<__half2*>(base + (long)r * ldc + cc) =
                        __floats2half2_rn(v00, v01);
                    *reinterpret_cast<__half2*>(base + (long)(r + 8) * ldc + cc) =
                        __floats2half2_rn(v10, v11);
                } else {                   // V: transposed into Vt
                    __half* base = Ch2 + (long)bz * c2Stride;
                    const int d = cc - 1024;
                    base[(long)d * S_TOK + r]           = __float2half_rn(v00);
                    base[(long)(d + 1) * S_TOK + r]     = __float2half_rn(v01);
                    base[(long)d * S_TOK + r + 8]       = __float2half_rn(v10);
                    base[(long)(d + 1) * S_TOK + r + 8] = __float2half_rn(v11);
                }
            }
        }
    }
}

// ---------------------------------------------------------------------------
// Prep: transpose x (B,C,S) fp32 -> xh (B,S,C) fp16
// ---------------------------------------------------------------------------
__global__ __launch_bounds__(256)
void transpose_x(const float* __restrict__ x, __half* __restrict__ xh)
{
    __shared__ float t[32][33];
    const int b = blockIdx.z;
    const int s0 = blockIdx.x << 5, c0 = blockIdx.y << 5;
    const float* xb = x + (long)b * C_DIM * S_TOK;
    const int a = threadIdx.x & 31, q8 = threadIdx.x >> 5;
    #pragma unroll
    for (int i = 0; i < 4; i++) {
        int cc = q8 + (i << 3);
        t[cc][a] = xb[(long)(c0 + cc) * S_TOK + s0 + a];
    }
    __syncthreads();
    const long ob = (long)b * S_TOK * C_DIM;
    #pragma unroll
    for (int i = 0; i < 4; i++) {
        int ss = q8 + (i << 3);
        xh[ob + (long)(s0 + ss) * C_DIM + c0 + a] = __float2half_rn(t[a][ss]);
    }
}

// Build concatenated QKV weights + bias (fp16 / fp32)
__global__ __launch_bounds__(256)
void prep_wqkv(const float* __restrict__ Wq, const float* __restrict__ Wk,
               const float* __restrict__ Wv, const float* __restrict__ bq,
               const float* __restrict__ bk, const float* __restrict__ bv,
               __half* __restrict__ Wqkv, float* __restrict__ bqkv)
{
    const int NW = D_DIM * C_DIM;
    int i = blockIdx.x * 256 + threadIdx.x;
    if (i < NW)               Wqkv[i] = __float2half_rn(Wq[i]);
    else if (i < 2 * NW)      Wqkv[i] = __float2half_rn(Wk[i - NW]);
    else if (i < 3 * NW)      Wqkv[i] = __float2half_rn(Wv[i - 2 * NW]);
    if (i < 512)              bqkv[i] = bq[i];
    else if (i < 1024)        bqkv[i] = bk[i - 512];
    else if (i < 1536)        bqkv[i] = bv[i - 1024];
}

// Split fp32 -> hi/lo fp16 (for Wo)
__global__ __launch_bounds__(256)
void split_mat(const float* __restrict__ w,
               __half* __restrict__ wh, __half* __restrict__ wl, int n)
{
    int i = blockIdx.x * 256 + threadIdx.x;
    if (i < n) {
        float v = w[i];
        __half h = __float2half_rn(v);
        wh[i] = h;
        wl[i] = __float2half_rn(v - __half2float(h));
    }
}

// ---------------------------------------------------------------------------
// Row sums of exp'd fp16 P -> inverse (fp32). One block per 4096-wide row.
// ---------------------------------------------------------------------------
__global__ __launch_bounds__(256)
void rowsum_inv(const __half* __restrict__ P, float* __restrict__ inv)
{
    const long row = blockIdx.x;
    const uint4* p4 = reinterpret_cast<const uint4*>(P + row * S_TOK);
    const int tid = threadIdx.x;

    float s = 0.f;
    #pragma unroll
    for (int i = 0; i < 2; i++) {
        uint4 raw = p4[tid + (i << 8)];
        const __half2* h = reinterpret_cast<const __half2*>(&raw);
        #pragma unroll
        for (int j = 0; j < 4; j++) {
            float2 f = __half22float2(h[j]);
            s += f.x + f.y;
        }
    }
    __shared__ float red[8];
    #pragma unroll
    for (int o = 16; o > 0; o >>= 1)
        s += __shfl_xor_sync(0xffffffffu, s, o);
    if ((tid & 31) == 0) red[tid >> 5] = s;
    __syncthreads();
    if (tid == 0) {
        float tot = red[0];
        #pragma unroll
        for (int w = 1; w < 8; w++) tot += red[w];
        inv[row] = 1.0f / tot;
    }
}

// ---------------------------------------------------------------------------
extern "C" void kernel_launch(void* const* d_in, const int* in_sizes, int n_in,
                              void* d_out, int out_size)
{
    const float* x  = (const float*)d_in[0];
    const float* Wq = (const float*)d_in[1];
    const float* bq = (const float*)d_in[2];
    const float* Wk = (const float*)d_in[3];
    const float* bk = (const float*)d_in[4];
    const float* Wv = (const float*)d_in[5];
    const float* bv = (const float*)d_in[6];
    const float* Wo = (const float*)d_in[7];
    const float* bo = (const float*)d_in[8];
    float* out = (float*)d_out;

    __half *xh, *Wqkv, *Woh, *Wol, *QKV, *Vt, *P, *O;
    float *bqkv, *InvS;
    cudaGetSymbolAddress((void**)&xh, g_xh);
    cudaGetSymbolAddress((void**)&Wqkv, g_Wqkv);
    cudaGetSymbolAddress((void**)&bqkv, g_bqkv);
    cudaGetSymbolAddress((void**)&Woh, g_Woh); cudaGetSymbolAddress((void**)&Wol, g_Wol);
    cudaGetSymbolAddress((void**)&QKV, g_QKV);
    cudaGetSymbolAddress((void**)&Vt, g_Vt);
    cudaGetSymbolAddress((void**)&P, g_P);
    cudaGetSymbolAddress((void**)&InvS, g_InvS);
    cudaGetSymbolAddress((void**)&O, g_O);

    const int S1 = 3 * 30720;
    const int S2 = 3 * 40960;
    cudaFuncSetAttribute(gemm<1,3>, cudaFuncAttributeMaxDynamicSharedMemorySize, S1);
    cudaFuncSetAttribute(gemm<1,1>, cudaFuncAttributeMaxDynamicSharedMemorySize, S1);
    cudaFuncSetAttribute(gemm<1,2>, cudaFuncAttributeMaxDynamicSharedMemorySize, S1);
    cudaFuncSetAttribute(gemm<2,0>, cudaFuncAttributeMaxDynamicSharedMemorySize, S2);

    const long SD  = (long)S_TOK * D_DIM;
    const long SS  = (long)S_TOK * S_TOK;
    const long SC  = (long)S_TOK * C_DIM;
    const long SQ  = (long)S_TOK * NQKV;
    const long CS  = (long)C_DIM * S_TOK;
    const float attn_scale = 0.044194173824159216f;   // 512^-0.5

    // ---- prep ----
    transpose_x<<<dim3(S_TOK / 32, C_DIM / 32, BATCH), 256>>>(x, xh);
    prep_wqkv<<<(3 * D_DIM * C_DIM + 255) / 256, 256>>>(Wq, Wk, Wv, bq, bk, bv, Wqkv, bqkv);
    split_mat<<<1024, 256>>>(Wo, Woh, Wol, C_DIM * D_DIM);

    // ---- fused QKV projection (N = 1536; Q scaled; V transposed) ----
    gemm<1,3><<<dim3(16, 12, BATCH), 256, S1>>>(
        xh, C_DIM, SC, C_DIM, Wqkv, nullptr, C_DIM, 0,
        nullptr, QKV, Vt, SQ, SD, NQKV, bqkv, nullptr, attn_scale);

    // ---- P = exp(Q K^T) ----
    gemm<1,1><<<dim3(16, 32, BATCH), 256, S1>>>(
        QKV, NQKV, SQ, D_DIM, QKV + 512, nullptr, NQKV, SQ,
        nullptr, P, nullptr, SS, 0, S_TOK, nullptr, nullptr, 1.f);

    // ---- inverse row sums ----
    rowsum_inv<<<BATCH * S_TOK, 256>>>(P, InvS);

    // ---- O = (P V) * invsum ----
    gemm<1,2><<<dim3(16, 4, BATCH), 256, S1>>>(
        P, S_TOK, SS, S_TOK, Vt, nullptr, S_TOK, SD,
        nullptr, O, nullptr, SD, 0, D_DIM, nullptr, InvS, 1.f);

    // ---- y = O Wo^T + bo (2-pass, fp32 transposed store) ----
    gemm<2,0><<<dim3(16, 4, BATCH), 256, S2>>>(
        O, D_DIM, SD, D_DIM, Woh, Wol, D_DIM, 0,
        out, nullptr, nullptr, CS, 0, S_TOK, bo, nullptr, 1.f);
}

// round 8
// speedup vs baseline: 6.2548x; 1.1046x over previous
#include <cuda_runtime.h>
#include <cuda_fp16.h>
#include <cstdint>

#define S_TOK 4096
#define C_DIM 512
#define D_DIM 512
#define BATCH 4
#define NQKV  1536

// ---------------------------------------------------------------------------
// Scratch (device globals; no allocations allowed)
// ---------------------------------------------------------------------------
__device__ __half g_xh[(size_t)BATCH * S_TOK * C_DIM];
__device__ __half g_Wqkv[NQKV * C_DIM];                  // rows: Wq | Wk | Wv
__device__ float  g_bqkv[NQKV];
__device__ __half g_Woh[C_DIM * D_DIM], g_Wol[C_DIM * D_DIM];
__device__ __half g_QKV[(size_t)BATCH * S_TOK * NQKV];   // cols: Q(scaled) | K
__device__ __half g_Vt[(size_t)BATCH * D_DIM * S_TOK];   // V^T (d-major)
__device__ __half g_P [(size_t)BATCH * S_TOK * S_TOK];   // exp(logits), fp16
__device__ float  g_InvS[(size_t)BATCH * S_TOK];         // 1 / row sums
__device__ __half g_O [(size_t)BATCH * S_TOK * D_DIM];

// ---------------------------------------------------------------------------
// PTX helpers (sm_103-portable: mma.sync / ldmatrix / cp.async only)
// ---------------------------------------------------------------------------
__device__ __forceinline__ uint32_t smem_u32(const void* p) {
    uint32_t a;
    asm("{ .reg .u64 t; cvta.to.shared.u64 t, %1; cvt.u32.u64 %0, t; }"
        : "=r"(a) : "l"(p));
    return a;
}

#define CP16(dst, src) \
    asm volatile("cp.async.cg.shared.global [%0], [%1], 16;" \
                 :: "r"(dst), "l"(src) : "memory")
#define CP_COMMIT() asm volatile("cp.async.commit_group;" ::: "memory")
#define CP_WAIT(n)  asm volatile("cp.async.wait_group %0;" :: "n"(n) : "memory")

#define LDSM_X4(r, addr)                                                      \
    asm volatile("ldmatrix.sync.aligned.m8n8.x4.shared.b16 {%0,%1,%2,%3}, [%4];" \
                 : "=r"((r)[0]), "=r"((r)[1]), "=r"((r)[2]), "=r"((r)[3])     \
                 : "r"(addr))

#define MMA16816(d, a, b0, b1)                                                \
    asm volatile("mma.sync.aligned.m16n8k16.row.col.f32.f16.f16.f32 "        \
                 "{%0,%1,%2,%3}, {%4,%5,%6,%7}, {%8,%9}, {%0,%1,%2,%3};"     \
                 : "+f"((d)[0]), "+f"((d)[1]), "+f"((d)[2]), "+f"((d)[3])    \
                 : "r"((a)[0]), "r"((a)[1]), "r"((a)[2]), "r"((a)[3]),       \
                   "r"(b0), "r"(b1))

// One full 64x32x16 warp pass: 4 mi x 4 n8 MMAs (bf has 2 LDSM groups)
#define MMA_PASS(af, bf)                                                      \
    _Pragma("unroll")                                                         \
    for (int mi = 0; mi < 4; mi++) {                                          \
        _Pragma("unroll")                                                     \
        for (int ng = 0; ng < 2; ng++) {                                      \
            MMA16816(acc[mi][2 * ng],     (af)[mi], (bf)[ng][0], (bf)[ng][1]); \
            MMA16816(acc[mi][2 * ng + 1], (af)[mi], (bf)[ng][2], (bf)[ng][3]); \
        }                                                                     \
    }

// ---------------------------------------------------------------------------
// fp16 mma.sync GEMM: acc(M,N) = sum_k A(m,k)*B(n,k); epilogue per OUTMODE.
// A,B k-contiguous with leading dims lda/ldb.
// APASS: 1 -> Ah*Bh ; 2 -> Ah*Bh + Ah*Bl (B split hi/lo)
// OUTMODE 0: fp32 transposed store, (acc+bias)*scale          (out-proj)
//         1: fp16 row store of exp(acc)                       (sim)
//         2: fp16 row store of acc * rowscale[row]            (PV)
//         3: QKV dispatch: n<1024 row fp16 (acc+bias)*(n<512?scale:1),
//            n>=1024 transposed fp16 to Ch2 (V^T)             (QKV proj)
// CTA 128(M) x 128(N), 8 warps of 64x32 (2 along M, 4 along N);
// K chunk 32; 3-stage cp.async, 1 barrier/chunk; 2 CTAs/SM.
// ---------------------------------------------------------------------------
template<int APASS, int OUTMODE>
__global__ __launch_bounds__(256, 2)
void gemm(const __half* __restrict__ Ah, int lda, long aStride, int Ktot,
          const __half* __restrict__ Bh, const __half* __restrict__ Bl,
          int ldb, long bStride,
          float* __restrict__ Cf, __half* __restrict__ Ch,
          __half* __restrict__ Ch2, long cStride, long c2Stride, int ldc,
          const float* __restrict__ bias, const float* __restrict__ rowscale,
          float scale)
{
    constexpr int AH_OFF = 0;
    constexpr int BH_OFF = 10240;                       // A tile = 128*80
    constexpr int BL_OFF = 20480;                       // APASS==2 only
    constexpr int STAGE  = (APASS == 2) ? 30720 : 20480;
    constexpr int NSTAGE = 3;

    extern __shared__ char smch[];
    const uint32_t sbase = smem_u32(smch);

    const int tid  = threadIdx.x;
    const int lane = tid & 31;
    const int wid  = tid >> 5;
    const int m0 = blockIdx.x * 128;
    const int n0 = blockIdx.y * 128;
    const int bz = blockIdx.z;

    const __half* ArowH = Ah + (long)bz * aStride + (long)m0 * lda;
    const __half* BrowH = Bh + (long)bz * bStride + (long)n0 * ldb;
    const __half* BrowL = (APASS == 2) ? (Bl + (long)bz * bStride + (long)n0 * ldb) : BrowH;

    const int ldrow = tid >> 2;     // 0..63
    const int ldq   = tid & 3;      // 16B quarter of 64B row
    auto stage_load = [&](int c, int buf) {
        const long kof = (long)c << 5;
        const uint32_t s0 = sbase + buf * STAGE;
        #pragma unroll
        for (int i = 0; i < 2; i++) {                 // A: 128 rows
            const int row = ldrow + i * 64;
            const uint32_t doff = (uint32_t)(row * 80 + ldq * 16);
            const long goff = (long)row * lda + kof + ldq * 8;
            CP16(s0 + AH_OFF + doff, ArowH + goff);
        }
        #pragma unroll
        for (int i = 0; i < 2; i++) {                 // B: 128 rows
            const int row = ldrow + i * 64;
            const uint32_t doff = (uint32_t)(row * 80 + ldq * 16);
            const long goff = (long)row * ldb + kof + ldq * 8;
            CP16(s0 + BH_OFF + doff, BrowH + goff);
            if (APASS == 2) CP16(s0 + BL_OFF + doff, BrowL + goff);
        }
    };

    float acc[4][4][4];
    #pragma unroll
    for (int i = 0; i < 4; i++)
        #pragma unroll
        for (int j = 0; j < 4; j++)
            #pragma unroll
            for (int q = 0; q < 4; q++) acc[i][j][q] = 0.f;

    const int wr = wid & 1;         // 2 warps along M (64 each)
    const int wc = wid >> 1;        // 4 warps along N (32 each)

    const uint32_t aAddr0 = (uint32_t)((wr * 64 + (lane & 15)) * 80 + ((lane >> 4) << 4));
    const uint32_t bAddr0 = (uint32_t)((wc * 32 + ((lane >> 4) << 3) + (lane & 7)) * 80
                                       + (((lane >> 3) & 1) << 4));

    const int nCh = Ktot >> 5;

    stage_load(0, 0); CP_COMMIT();
    stage_load(1, 1); CP_COMMIT();

    int bufc = 0;
    for (int c = 0; c < nCh; c++) {
        if (c + 1 < nCh) { CP_WAIT(1); } else { CP_WAIT(0); }
        __syncthreads();            // chunk c visible; buffer (bufc+2)%3 free
        const uint32_t s0 = sbase + bufc * STAGE;
        #pragma unroll
        for (int k16 = 0; k16 < 2; k16++) {
            const uint32_t aA = s0 + AH_OFF + aAddr0 + k16 * 32;
            const uint32_t bA = s0 + BH_OFF + bAddr0 + k16 * 32;

            uint32_t ah[4][4], bb[2][4];
            #pragma unroll
            for (int mi = 0; mi < 4; mi++) LDSM_X4(ah[mi], aA + mi * 1280);
            #pragma unroll
            for (int ng = 0; ng < 2; ng++) LDSM_X4(bb[ng], bA + ng * 1280);

            MMA_PASS(ah, bb);                         // Ah * Bh

            if (APASS == 2) {
                #pragma unroll
                for (int ng = 0; ng < 2; ng++)
                    LDSM_X4(bb[ng], bA + (BL_OFF - BH_OFF) + ng * 1280);
                MMA_PASS(ah, bb);                     // Ah * Bl
            }
        }
        if (c + 2 < nCh) {
            int b2 = bufc + 2; if (b2 >= NSTAGE) b2 -= NSTAGE;
            stage_load(c + 2, b2);
        }
        CP_COMMIT();
        if (++bufc == NSTAGE) bufc = 0;
    }

    // ---- epilogue ----
    const int tq = lane >> 2;
    const int tr = lane & 3;

    #pragma unroll
    for (int mi = 0; mi < 4; mi++) {
        const int r = m0 + wr * 64 + mi * 16 + tq;
        float inv0 = 1.f, inv1 = 1.f;
        if (OUTMODE == 2) {
            inv0 = rowscale[(long)bz * S_TOK + r];
            inv1 = rowscale[(long)bz * S_TOK + r + 8];
        }
        #pragma unroll
        for (int n8 = 0; n8 < 4; n8++) {
            const int cc = n0 + wc * 32 + n8 * 8 + tr * 2;

            if (OUTMODE == 0) {            // fp32 transposed + bias
                const float b0 = bias[cc], b1 = bias[cc + 1];
                float* base = Cf + (long)bz * cStride;
                base[(long)cc * ldc + r]           = (acc[mi][n8][0] + b0) * scale;
                base[(long)(cc + 1) * ldc + r]     = (acc[mi][n8][1] + b1) * scale;
                base[(long)cc * ldc + r + 8]       = (acc[mi][n8][2] + b0) * scale;
                base[(long)(cc + 1) * ldc + r + 8] = (acc[mi][n8][3] + b1) * scale;
            } else if (OUTMODE == 1) {     // exp, fp16 row
                __half* base = Ch + (long)bz * cStride;
                *reinterpret_cast<__half2*>(base + (long)r * ldc + cc) =
                    __floats2half2_rn(__expf(acc[mi][n8][0]), __expf(acc[mi][n8][1]));
                *reinterpret_cast<__half2*>(base + (long)(r + 8) * ldc + cc) =
                    __floats2half2_rn(__expf(acc[mi][n8][2]), __expf(acc[mi][n8][3]));
            } else if (OUTMODE == 2) {     // row-scaled, fp16 row
                __half* base = Ch + (long)bz * cStride;
                *reinterpret_cast<__half2*>(base + (long)r * ldc + cc) =
                    __floats2half2_rn(acc[mi][n8][0] * inv0, acc[mi][n8][1] * inv0);
                *reinterpret_cast<__half2*>(base + (long)(r + 8) * ldc + cc) =
                    __floats2half2_rn(acc[mi][n8][2] * inv1, acc[mi][n8][3] * inv1);
            } else {                       // OUTMODE 3: QKV dispatch
                const float b0 = bias[cc], b1 = bias[cc + 1];
                const float sc = (n0 < 512) ? scale : 1.f;
                const float v00 = (acc[mi][n8][0] + b0) * sc;
                const float v01 = (acc[mi][n8][1] + b1) * sc;
                const float v10 = (acc[mi][n8][2] + b0) * sc;
                const float v11 = (acc[mi][n8][3] + b1) * sc;
                if (n0 < 1024) {           // Q | K: row-major into QKV
                    __half* base = Ch + (long)bz * cStride;
                    *reinterpret_cast<__half2*>(base + (long)r * ldc + cc) =
                        __floats2half2_rn(v00, v01);
                    *reinterpret_cast<__half2*>(base + (long)(r + 8) * ldc + cc) =
                        __floats2half2_rn(v10, v11);
                } else {                   // V: transposed into Vt
                    __half* base = Ch2 + (long)bz * c2Stride;
                    const int d = cc - 1024;
                    base[(long)d * S_TOK + r]           = __float2half_rn(v00);
                    base[(long)(d + 1) * S_TOK + r]     = __float2half_rn(v01);
                    base[(long)d * S_TOK + r + 8]       = __float2half_rn(v10);
                    base[(long)(d + 1) * S_TOK + r + 8] = __float2half_rn(v11);
                }
            }
        }
    }
}

// ---------------------------------------------------------------------------
// Prep: transpose x (B,C,S) fp32 -> xh (B,S,C) fp16
// ---------------------------------------------------------------------------
__global__ __launch_bounds__(256)
void transpose_x(const float* __restrict__ x, __half* __restrict__ xh)
{
    __shared__ float t[32][33];
    const int b = blockIdx.z;
    const int s0 = blockIdx.x << 5, c0 = blockIdx.y << 5;
    const float* xb = x + (long)b * C_DIM * S_TOK;
    const int a = threadIdx.x & 31, q8 = threadIdx.x >> 5;
    #pragma unroll
    for (int i = 0; i < 4; i++) {
        int cc = q8 + (i << 3);
        t[cc][a] = xb[(long)(c0 + cc) * S_TOK + s0 + a];
    }
    __syncthreads();
    const long ob = (long)b * S_TOK * C_DIM;
    #pragma unroll
    for (int i = 0; i < 4; i++) {
        int ss = q8 + (i << 3);
        xh[ob + (long)(s0 + ss) * C_DIM + c0 + a] = __float2half_rn(t[a][ss]);
    }
}

// Build concatenated QKV weights + bias (fp16 / fp32)
__global__ __launch_bounds__(256)
void prep_wqkv(const float* __restrict__ Wq, const float* __restrict__ Wk,
               const float* __restrict__ Wv, const float* __restrict__ bq,
               const float* __restrict__ bk, const float* __restrict__ bv,
               __half* __restrict__ Wqkv, float* __restrict__ bqkv)
{
    const int NW = D_DIM * C_DIM;
    int i = blockIdx.x * 256 + threadIdx.x;
    if (i < NW)               Wqkv[i] = __float2half_rn(Wq[i]);
    else if (i < 2 * NW)      Wqkv[i] = __float2half_rn(Wk[i - NW]);
    else if (i < 3 * NW)      Wqkv[i] = __float2half_rn(Wv[i - 2 * NW]);
    if (i < 512)              bqkv[i] = bq[i];
    else if (i < 1024)        bqkv[i] = bk[i - 512];
    else if (i < 1536)        bqkv[i] = bv[i - 1024];
}

// Split fp32 -> hi/lo fp16 (for Wo)
__global__ __launch_bounds__(256)
void split_mat(const float* __restrict__ w,
               __half* __restrict__ wh, __half* __restrict__ wl, int n)
{
    int i = blockIdx.x * 256 + threadIdx.x;
    if (i < n) {
        float v = w[i];
        __half h = __float2half_rn(v);
        wh[i] = h;
        wl[i] = __float2half_rn(v - __half2float(h));
    }
}

// ---------------------------------------------------------------------------
// Row sums of exp'd fp16 P -> inverse (fp32). One block per 4096-wide row.
// ---------------------------------------------------------------------------
__global__ __launch_bounds__(256)
void rowsum_inv(const __half* __restrict__ P, float* __restrict__ inv)
{
    const long row = blockIdx.x;
    const uint4* p4 = reinterpret_cast<const uint4*>(P + row * S_TOK);
    const int tid = threadIdx.x;

    float s = 0.f;
    #pragma unroll
    for (int i = 0; i < 2; i++) {
        uint4 raw = p4[tid + (i << 8)];
        const __half2* h = reinterpret_cast<const __half2*>(&raw);
        #pragma unroll
        for (int j = 0; j < 4; j++) {
            float2 f = __half22float2(h[j]);
            s += f.x + f.y;
        }
    }
    __shared__ float red[8];
    #pragma unroll
    for (int o = 16; o > 0; o >>= 1)
        s += __shfl_xor_sync(0xffffffffu, s, o);
    if ((tid & 31) == 0) red[tid >> 5] = s;
    __syncthreads();
    if (tid == 0) {
        float tot = red[0];
        #pragma unroll
        for (int w = 1; w < 8; w++) tot += red[w];
        inv[row] = 1.0f / tot;
    }
}

// ---------------------------------------------------------------------------
extern "C" void kernel_launch(void* const* d_in, const int* in_sizes, int n_in,
                              void* d_out, int out_size)
{
    const float* x  = (const float*)d_in[0];
    const float* Wq = (const float*)d_in[1];
    const float* bq = (const float*)d_in[2];
    const float* Wk = (const float*)d_in[3];
    const float* bk = (const float*)d_in[4];
    const float* Wv = (const float*)d_in[5];
    const float* bv = (const float*)d_in[6];
    const float* Wo = (const float*)d_in[7];
    const float* bo = (const float*)d_in[8];
    float* out = (float*)d_out;

    __half *xh, *Wqkv, *Woh, *Wol, *QKV, *Vt, *P, *O;
    float *bqkv, *InvS;
    cudaGetSymbolAddress((void**)&xh, g_xh);
    cudaGetSymbolAddress((void**)&Wqkv, g_Wqkv);
    cudaGetSymbolAddress((void**)&bqkv, g_bqkv);
    cudaGetSymbolAddress((void**)&Woh, g_Woh); cudaGetSymbolAddress((void**)&Wol, g_Wol);
    cudaGetSymbolAddress((void**)&QKV, g_QKV);
    cudaGetSymbolAddress((void**)&Vt, g_Vt);
    cudaGetSymbolAddress((void**)&P, g_P);
    cudaGetSymbolAddress((void**)&InvS, g_InvS);
    cudaGetSymbolAddress((void**)&O, g_O);

    const int S1 = 3 * 20480;      // 1-pass stage set
    const int S2 = 3 * 30720;      // 2-pass stage set
    cudaFuncSetAttribute(gemm<1,3>, cudaFuncAttributeMaxDynamicSharedMemorySize, S1);
    cudaFuncSetAttribute(gemm<1,1>, cudaFuncAttributeMaxDynamicSharedMemorySize, S1);
    cudaFuncSetAttribute(gemm<1,2>, cudaFuncAttributeMaxDynamicSharedMemorySize, S1);
    cudaFuncSetAttribute(gemm<2,0>, cudaFuncAttributeMaxDynamicSharedMemorySize, S2);

    const long SD  = (long)S_TOK * D_DIM;
    const long SS  = (long)S_TOK * S_TOK;
    const long SC  = (long)S_TOK * C_DIM;
    const long SQ  = (long)S_TOK * NQKV;
    const long CS  = (long)C_DIM * S_TOK;
    const float attn_scale = 0.044194173824159216f;   // 512^-0.5

    // ---- prep ----
    transpose_x<<<dim3(S_TOK / 32, C_DIM / 32, BATCH), 256>>>(x, xh);
    prep_wqkv<<<(3 * D_DIM * C_DIM + 255) / 256, 256>>>(Wq, Wk, Wv, bq, bk, bv, Wqkv, bqkv);
    split_mat<<<1024, 256>>>(Wo, Woh, Wol, C_DIM * D_DIM);

    // ---- fused QKV projection (N = 1536; Q scaled; V transposed) ----
    gemm<1,3><<<dim3(32, 12, BATCH), 256, S1>>>(
        xh, C_DIM, SC, C_DIM, Wqkv, nullptr, C_DIM, 0,
        nullptr, QKV, Vt, SQ, SD, NQKV, bqkv, nullptr, attn_scale);

    // ---- P = exp(Q K^T) ----
    gemm<1,1><<<dim3(32, 32, BATCH), 256, S1>>>(
        QKV, NQKV, SQ, D_DIM, QKV + 512, nullptr, NQKV, SQ,
        nullptr, P, nullptr, SS, 0, S_TOK, nullptr, nullptr, 1.f);

    // ---- inverse row sums ----
    rowsum_inv<<<BATCH * S_TOK, 256>>>(P, InvS);

    // ---- O = (P V) * invsum ----
    gemm<1,2><<<dim3(32, 4, BATCH), 256, S1>>>(
        P, S_TOK, SS, S_TOK, Vt, nullptr, S_TOK, SD,
        nullptr, O, nullptr, SD, 0, D_DIM, nullptr, InvS, 1.f);

    // ---- y = O Wo^T + bo (2-pass, fp32 transposed store) ----
    gemm<2,0><<<dim3(32, 4, BATCH), 256, S2>>>(
        O, D_DIM, SD, D_DIM, Woh, Wol, D_DIM, 0,
        out, nullptr, nullptr, CS, 0, S_TOK, bo, nullptr, 1.f);
}